// round 6
// baseline (speedup 1.0000x reference)
#include <cuda_runtime.h>
#include <math.h>
#include <stdint.h>

// Problem constants (fixed by the reference)
#define Nn 100000
#define Ee 400000
#define Rr 4
#define Gg 64
#define INF 64
#define Hh 128
#define Cc 2

// ---------------- scratch (device globals; no allocation allowed) ----------
__device__ float g_h0  [(size_t)Nn * Hh];   // relu(x@W_in + b_in)
__device__ float g_Y   [(size_t)Nn * Hh];   // per-relation GEMM output
__device__ float g_out1[(size_t)Nn * Hh];   // layer-1 scatter sum (raw, no bias)
__device__ float g_out2[(size_t)Nn * Hh];   // layer-2 scatter sum (raw, no bias)
__device__ float g_rsq_out[Rr * Nn];
__device__ float g_rsq_in [Rr * Nn];
__device__ float g_pool[Gg * Hh];
__device__ float g_cnt [Gg];
// transposed + tf32 hi/lo split weights: [(l*4+r)][hilo][n(128)][k(128)]
__device__ float g_wt   [2 * Rr * 2 * Hh * Hh];
// input weights: [hilo][n(128)][k(64)]
__device__ float g_wt_in[2 * Hh * INF];
__device__ float g_bsum [2 * Hh];   // per-layer sum of relation biases

// ---------------- tf32 helpers ----------------------------------------------
__device__ __forceinline__ float tf32_rna(float x) {
    uint32_t h;
    asm("cvt.rna.tf32.f32 %0, %1;" : "=r"(h) : "f"(x));
    return __uint_as_float(h);
}

// ---------------- prep kernels ----------------------------------------------
__global__ void wprep_kernel(const float* __restrict__ W1,
                             const float* __restrict__ W2,
                             const float* __restrict__ Win) {
    int i = blockIdx.x * blockDim.x + threadIdx.x;
    const int TL = Rr * Hh * Hh;  // 65536
    if (i < 2 * TL) {
        int l = i / TL, j = i % TL;
        int r = j >> 14;
        int k = (j >> 7) & 127;
        int n = j & 127;
        float w = (l == 0 ? W1 : W2)[j];
        float hi = tf32_rna(w);
        size_t base = (size_t)((l * Rr + r) * 2) * (Hh * Hh);
        g_wt[base + (size_t)n * Hh + k] = hi;
        g_wt[base + Hh * Hh + (size_t)n * Hh + k] = tf32_rna(w - hi);
    } else {
        int j = i - 2 * TL;
        if (j < INF * Hh) {
            int k = j >> 7, n = j & 127;
            float w = Win[j];
            float hi = tf32_rna(w);
            g_wt_in[n * INF + k] = hi;
            g_wt_in[Hh * INF + n * INF + k] = tf32_rna(w - hi);
        }
    }
}

__global__ void bsum_kernel(const float* __restrict__ b1,
                            const float* __restrict__ b2) {
    int j = threadIdx.x;
    if (j < Hh) {
        float s1 = 0.f, s2 = 0.f;
        for (int r = 0; r < Rr; ++r) { s1 += b1[r * Hh + j]; s2 += b2[r * Hh + j]; }
        g_bsum[j] = s1; g_bsum[Hh + j] = s2;
    }
}

// ---------------- degrees ---------------------------------------------------
__global__ void degree_kernel(const int* __restrict__ src, const int* __restrict__ dst) {
    int i = blockIdx.x * blockDim.x + threadIdx.x;
    if (i < Rr * Ee) {
        int r = i / Ee;
        atomicAdd(&g_rsq_out[r * Nn + src[i]], 1.f);
        atomicAdd(&g_rsq_in [r * Nn + dst[i]], 1.f);
    }
}
__global__ void rsq_kernel() {
    int i = blockIdx.x * blockDim.x + threadIdx.x;
    if (i < Rr * Nn) {
        g_rsq_out[i] = rsqrtf(fmaxf(g_rsq_out[i], 1.f));
        g_rsq_in [i] = rsqrtf(fmaxf(g_rsq_in [i], 1.f));
    }
}

// ---------------- edge scatter (post-GEMM, both scales at edge) -------------
// out[d] += Y[s] * rso[s] * rsi[d]
__device__ __forceinline__ void red_add_v4(float* p, float4 v) {
    asm volatile(
        "{\n\t.reg .u64 pg;\n\t"
        "cvta.to.global.u64 pg, %0;\n\t"
        "red.global.add.v4.f32 [pg], {%1,%2,%3,%4};\n\t}"
        :: "l"(p), "f"(v.x), "f"(v.y), "f"(v.z), "f"(v.w) : "memory");
}

__global__ void scatter_kernel(const float* __restrict__ Y,
                               const int*   __restrict__ src,
                               const int*   __restrict__ dst,
                               const float* __restrict__ rso,
                               const float* __restrict__ rsi,
                               float*       __restrict__ out) {
    int t = blockIdx.x * blockDim.x + threadIdx.x;
    int e = t >> 5;
    int lane = t & 31;
    if (e >= Ee) return;
    int s = __ldg(&src[e]);
    int d = __ldg(&dst[e]);
    float sc = __ldg(&rso[s]) * __ldg(&rsi[d]);
    float4 v = *(const float4*)&Y[(size_t)s * Hh + lane * 4];
    v.x *= sc; v.y *= sc; v.z *= sc; v.w *= sc;
    red_add_v4(&out[(size_t)d * Hh + lane * 4], v);
}

// ---------------- tf32 mma.sync GEMM (3xTF32, vectorized fragments) ----------
// C[row,128] = relu?( rawA-or-relu(A+abias) @ (W_hi + W_lo)^T + cbias )
// Virtual K'=3K passes: rna(A)xW_hi, rna(A-rna(A))xW_hi, rna(A)xW_lo.
// SMEM tile layout: [row][k%4][k/4] with row stride 36 floats -> per-thread
// fragments are contiguous: A via LDS.128, B via LDS.64 pairs.
// Tile 128(M)x128(N), BK=32, 256 threads = 8 warps in 4(M)x2(N).
#define SMS 36
#define TILE_F (128 * SMS)   // 4608 floats per tile buffer

__device__ __forceinline__ void mma8(float* c, const uint32_t* a,
                                     uint32_t b0, uint32_t b1) {
    asm volatile(
        "mma.sync.aligned.m16n8k8.row.col.f32.tf32.tf32.f32 "
        "{%0,%1,%2,%3}, {%4,%5,%6,%7}, {%8,%9}, {%0,%1,%2,%3};"
        : "+f"(c[0]), "+f"(c[1]), "+f"(c[2]), "+f"(c[3])
        : "r"(a[0]), "r"(a[1]), "r"(a[2]), "r"(a[3]), "r"(b0), "r"(b1));
}

template <int AMODE>   // 0: raw A, 1: relu(A + abias[col])
__global__ void __launch_bounds__(256)
mma_gemm_kernel(const float* __restrict__ A, int K,
                const float* __restrict__ Wt,      // [2][128][K] hi then lo (tf32)
                const float* __restrict__ abias,   // [K] for AMODE=1
                const float* __restrict__ cbias,   // nullable [128]
                float* __restrict__ C,
                int n, int relu_out) {
    extern __shared__ float sm[];
    float* As = sm;                 // [2][TILE_F]
    float* Bs = sm + 2 * TILE_F;    // [2][TILE_F]

    const int tid  = threadIdx.x;
    const int lane = tid & 31, warp = tid >> 5;
    const int wm = warp >> 1, wn = warp & 1;
    const int g = lane >> 2, t = lane & 3;
    const int row0 = blockIdx.x * 128;
    const int kdiv = K >> 5;
    const int NC = 3 * kdiv;

    const int sr  = tid >> 1;          // staged row 0..127
    const int sc  = (tid & 1) * 16;    // staged col base
    const int sc4 = (tid & 1) * 4;     // staged j base
    const int grow_s = row0 + sr;

    float acc[2][8][4];
#pragma unroll
    for (int mf = 0; mf < 2; ++mf)
#pragma unroll
        for (int nf = 0; nf < 8; ++nf)
#pragma unroll
            for (int q = 0; q < 4; ++q) acc[mf][nf][q] = 0.f;

    float fa[16], fb[16];

    // stage chunk (sel, kk0) into fa/fb registers
#define STAGE(SEL, KK0) do {                                                   \
    const float* bp = Wt + ((SEL) == 2 ? (size_t)128 * K : 0)                  \
                    + (size_t)sr * K + (KK0) + sc;                             \
    _Pragma("unroll")                                                          \
    for (int q = 0; q < 4; ++q) {                                              \
        float4 v = make_float4(0.f, 0.f, 0.f, 0.f);                            \
        if (grow_s < n) {                                                      \
            v = *(const float4*)(A + (size_t)grow_s * K + (KK0) + sc + q * 4); \
            if (AMODE == 1) {                                                  \
                float4 bb = *(const float4*)(abias + (KK0) + sc + q * 4);      \
                v.x = fmaxf(v.x + bb.x, 0.f); v.y = fmaxf(v.y + bb.y, 0.f);    \
                v.z = fmaxf(v.z + bb.z, 0.f); v.w = fmaxf(v.w + bb.w, 0.f);    \
            }                                                                  \
        }                                                                      \
        const float* fv = (const float*)&v;                                    \
        _Pragma("unroll")                                                      \
        for (int i = 0; i < 4; ++i) {                                          \
            float x  = fv[i];                                                  \
            float xh = tf32_rna(x);                                            \
            fa[q * 4 + i] = ((SEL) == 1) ? tf32_rna(x - xh) : xh;              \
        }                                                                      \
        float4 w = *(const float4*)(bp + q * 4);                               \
        fb[q * 4 + 0] = w.x; fb[q * 4 + 1] = w.y;                              \
        fb[q * 4 + 2] = w.z; fb[q * 4 + 3] = w.w;                              \
    }                                                                          \
} while (0)

    // store fa/fb (register transpose) into buffer BUF
#define STORE(BUF) do {                                                        \
    float* a_d = As + (BUF) * TILE_F + sr * SMS + sc4;                         \
    float* b_d = Bs + (BUF) * TILE_F + sr * SMS + sc4;                         \
    _Pragma("unroll")                                                          \
    for (int i = 0; i < 4; ++i) {                                              \
        float4 wa = make_float4(fa[i], fa[4 + i], fa[8 + i], fa[12 + i]);      \
        float4 wb = make_float4(fb[i], fb[4 + i], fb[8 + i], fb[12 + i]);      \
        *(float4*)(a_d + i * 8) = wa;                                          \
        *(float4*)(b_d + i * 8) = wb;                                          \
    }                                                                          \
} while (0)

    STAGE(0, 0);
    STORE(0);
    __syncthreads();

    for (int c = 0; c < NC; ++c) {
        const int buf = c & 1;
        const bool pf = (c + 1) < NC;
        if (pf) {
            int c1 = c + 1;
            int sel = c1 / kdiv;
            int kk0 = (c1 - sel * kdiv) * 32;
            STAGE(sel, kk0);
        }
        // compute on current buffer
        const float* a_s = As + buf * TILE_F;
        const float* b_s = Bs + buf * TILE_F;
        float av[2][2][8];
#pragma unroll
        for (int mf = 0; mf < 2; ++mf)
#pragma unroll
            for (int rr = 0; rr < 2; ++rr) {
                int row = wm * 32 + mf * 16 + rr * 8 + g;
                const float* p = a_s + row * SMS + t * 8;
                *(float4*)&av[mf][rr][0] = *(const float4*)(p);
                *(float4*)&av[mf][rr][4] = *(const float4*)(p + 4);
            }
#pragma unroll
        for (int ks = 0; ks < 4; ++ks) {
            const int j0 = 2 * ks;
            uint32_t afr[2][4];
#pragma unroll
            for (int mf = 0; mf < 2; ++mf) {
                afr[mf][0] = __float_as_uint(av[mf][0][j0]);
                afr[mf][1] = __float_as_uint(av[mf][1][j0]);
                afr[mf][2] = __float_as_uint(av[mf][0][j0 + 1]);
                afr[mf][3] = __float_as_uint(av[mf][1][j0 + 1]);
            }
#pragma unroll
            for (int nf = 0; nf < 8; ++nf) {
                int nr = wn * 64 + nf * 8 + g;
                float2 b2 = *(const float2*)(b_s + nr * SMS + t * 8 + j0);
                uint32_t b0 = __float_as_uint(b2.x);
                uint32_t b1 = __float_as_uint(b2.y);
                mma8(acc[0][nf], afr[0], b0, b1);
                mma8(acc[1][nf], afr[1], b0, b1);
            }
        }
        if (pf) {
            __syncthreads();
            STORE((c + 1) & 1);
            __syncthreads();
        }
    }

    // ---- epilogue
#pragma unroll
    for (int mf = 0; mf < 2; ++mf) {
#pragma unroll
        for (int half = 0; half < 2; ++half) {
            int grow = row0 + wm * 32 + mf * 16 + g + half * 8;
            if (grow >= n) continue;
            float* crow = C + (size_t)grow * 128;
#pragma unroll
            for (int nf = 0; nf < 8; ++nf) {
                int col = wn * 64 + nf * 8 + 2 * t;
                float v0 = acc[mf][nf][half * 2 + 0];
                float v1 = acc[mf][nf][half * 2 + 1];
                if (cbias) { v0 += cbias[col]; v1 += cbias[col + 1]; }
                if (relu_out) { v0 = fmaxf(v0, 0.f); v1 = fmaxf(v1, 0.f); }
                float2 v; v.x = v0; v.y = v1;
                *(float2*)(crow + col) = v;
            }
        }
    }
#undef STAGE
#undef STORE
}

// ---------------- pooling ----------------------------------------------------
__global__ void count_kernel(const int* __restrict__ gid) {
    int i = blockIdx.x * blockDim.x + threadIdx.x;
    if (i < Nn) atomicAdd(&g_cnt[gid[i]], 1.f);
}
__global__ void pool_kernel(const float* __restrict__ h, const int* __restrict__ gid) {
    int t = blockIdx.x * blockDim.x + threadIdx.x;
    int node = t >> 5;
    int lane = t & 31;
    if (node >= Nn) return;
    int g = __ldg(&gid[node]);
    float4 v = *(const float4*)&h[(size_t)node * Hh + lane * 4];
    red_add_v4(&g_pool[g * Hh + lane * 4], v);
}

// ---------------- MLP head (single block) -------------------------------------
__global__ void mlp_kernel(const float* __restrict__ Wm1, const float* __restrict__ bm1,
                           const float* __restrict__ Wm2, const float* __restrict__ bm2,
                           const float* __restrict__ Wm3, const float* __restrict__ bm3,
                           float* __restrict__ out) {
    __shared__ float z[Gg * Hh];
    int tid = threadIdx.x;   // 256
    // mean pool + layer-2 bias sum (mean(x + b) = mean(x) + b)
    for (int i = tid; i < Gg * Hh; i += 256)
        z[i] = g_pool[i] / fmaxf(g_cnt[i >> 7], 1.f) + g_bsum[Hh + (i & 127)];
    __syncthreads();
    float r1[32];
#pragma unroll
    for (int t = 0; t < 32; ++t) {
        int o = tid + t * 256, g = o >> 7, j = o & 127;
        float s = bm1[j];
        for (int k = 0; k < Hh; ++k) s += z[(g << 7) + k] * Wm1[k * Hh + j];
        r1[t] = fmaxf(s, 0.f);
    }
    __syncthreads();
#pragma unroll
    for (int t = 0; t < 32; ++t) z[tid + t * 256] = r1[t];
    __syncthreads();
#pragma unroll
    for (int t = 0; t < 32; ++t) {
        int o = tid + t * 256, g = o >> 7, j = o & 127;
        float s = bm2[j];
        for (int k = 0; k < Hh; ++k) s += z[(g << 7) + k] * Wm2[k * Hh + j];
        r1[t] = fmaxf(s, 0.f);
    }
    __syncthreads();
#pragma unroll
    for (int t = 0; t < 32; ++t) z[tid + t * 256] = r1[t];
    __syncthreads();
    if (tid < Gg * Cc) {
        int g = tid >> 1, c = tid & 1;
        float s = bm3[c];
        for (int k = 0; k < Hh; ++k) s += z[(g << 7) + k] * Wm3[k * Cc + c];
        out[tid] = s;
    }
}

// ---------------- launch -------------------------------------------------------
static float* sym(const void* s) {
    void* p = nullptr;
    cudaGetSymbolAddress(&p, s);
    return (float*)p;
}

extern "C" void kernel_launch(void* const* d_in, const int* in_sizes, int n_in,
                              void* d_out, int out_size) {
    const float* x    = (const float*)d_in[0];
    const int*   src  = (const int*)  d_in[1];
    const int*   dst  = (const int*)  d_in[2];
    const int*   gid  = (const int*)  d_in[3];
    const float* W_in = (const float*)d_in[4];
    const float* b_in = (const float*)d_in[5];
    const float* W1   = (const float*)d_in[6];
    const float* b1   = (const float*)d_in[7];
    const float* W2   = (const float*)d_in[8];
    const float* b2   = (const float*)d_in[9];
    const float* Wm1  = (const float*)d_in[10];
    const float* bm1  = (const float*)d_in[11];
    const float* Wm2  = (const float*)d_in[12];
    const float* bm2  = (const float*)d_in[13];
    const float* Wm3  = (const float*)d_in[14];
    const float* bm3  = (const float*)d_in[15];
    float* out = (float*)d_out;

    float* p_h0   = sym(g_h0);
    float* p_Y    = sym(g_Y);
    float* p_out1 = sym(g_out1);
    float* p_out2 = sym(g_out2);
    float* p_rso  = sym(g_rsq_out);
    float* p_rsi  = sym(g_rsq_in);
    float* p_pool = sym(g_pool);
    float* p_cnt  = sym(g_cnt);
    float* p_wt   = sym(g_wt);
    float* p_wtin = sym(g_wt_in);
    float* p_bsum = sym(g_bsum);

    const int TB = 256;
    const int gemm_blocks = (Nn + 127) / 128;      // 782
    const int scat_blocks = (Ee * 32 + TB - 1) / TB;
    const int smem_gemm = 4 * TILE_F * 4;          // 73728 bytes

    cudaFuncSetAttribute(mma_gemm_kernel<0>,
                         cudaFuncAttributeMaxDynamicSharedMemorySize, smem_gemm);
    cudaFuncSetAttribute(mma_gemm_kernel<1>,
                         cudaFuncAttributeMaxDynamicSharedMemorySize, smem_gemm);

    // zeroing (memset nodes, not kernels)
    cudaMemsetAsync(p_rso, 0, (size_t)Rr * Nn * sizeof(float));
    cudaMemsetAsync(p_rsi, 0, (size_t)Rr * Nn * sizeof(float));
    cudaMemsetAsync(p_out1, 0, (size_t)Nn * Hh * sizeof(float));
    cudaMemsetAsync(p_out2, 0, (size_t)Nn * Hh * sizeof(float));
    cudaMemsetAsync(p_pool, 0, (size_t)Gg * Hh * sizeof(float));
    cudaMemsetAsync(p_cnt, 0, (size_t)Gg * sizeof(float));

    // degrees -> rsqrt
    degree_kernel<<<(Rr * Ee + TB - 1) / TB, TB>>>(src, dst);           // k1
    rsq_kernel<<<(Rr * Nn + TB - 1) / TB, TB>>>();                      // k2

    // weight prep + bias sums
    wprep_kernel<<<(2 * Rr * Hh * Hh + INF * Hh + TB - 1) / TB, TB>>>(W1, W2, W_in); // k3
    bsum_kernel<<<1, 128>>>(b1, b2);                                    // k4

    // h0 = relu(x @ W_in + b_in)                                        k5
    mma_gemm_kernel<0><<<gemm_blocks, 256, smem_gemm>>>(
        x, INF, p_wtin, nullptr, b_in, p_h0, Nn, 1);

    // layer 1: for each relation, Y = h0 @ W1_r, then edge-scatter into out1
    for (int r = 0; r < Rr; ++r) {
        mma_gemm_kernel<0><<<gemm_blocks, 256, smem_gemm>>>(            // k6 = first
            p_h0, Hh, p_wt + (size_t)(0 * Rr + r) * 2 * Hh * Hh,
            nullptr, nullptr, p_Y, Nn, 0);
        scatter_kernel<<<scat_blocks, TB>>>(p_Y, src + r * Ee, dst + r * Ee,
                                            p_rso + r * Nn, p_rsi + r * Nn, p_out1);
    }

    // layer 2: A = relu(out1 + bsum1) fused into GEMM A-load
    for (int r = 0; r < Rr; ++r) {
        mma_gemm_kernel<1><<<gemm_blocks, 256, smem_gemm>>>(
            p_out1, Hh, p_wt + (size_t)(1 * Rr + r) * 2 * Hh * Hh,
            p_bsum, nullptr, p_Y, Nn, 0);
        scatter_kernel<<<scat_blocks, TB>>>(p_Y, src + r * Ee, dst + r * Ee,
                                            p_rso + r * Nn, p_rsi + r * Nn, p_out2);
    }

    // per-graph mean pool (bias folded into mlp z-init)
    count_kernel<<<(Nn + TB - 1) / TB, TB>>>(gid);
    pool_kernel<<<(Nn * 32 + TB - 1) / TB, TB>>>(p_out2, gid);

    // MLP head
    mlp_kernel<<<1, TB>>>(Wm1, bm1, Wm2, bm2, Wm3, bm3, out);
}

// round 7
// speedup vs baseline: 1.6989x; 1.6989x over previous
#include <cuda_runtime.h>
#include <cuda_bf16.h>
#include <math.h>
#include <stdint.h>

// Problem constants (fixed by the reference)
#define Nn 100000
#define Ee 400000
#define Rr 4
#define Gg 64
#define INF 64
#define Hh 128
#define Cc 2

#define WSZ    (2 * Hh * 64)   // u32 per relation weight (hi+lo planes, KU=64)
#define WSZ_IN (2 * Hh * 32)   // input weight (KU=32)

// ---------------- scratch (device globals; no allocation allowed) ----------
__device__ float g_h0  [(size_t)Nn * Hh];        // relu(x@W_in + b_in)
__device__ float g_Y   [(size_t)Rr * Nn * Hh];   // per-relation GEMM outputs
__device__ float g_out1[(size_t)Nn * Hh];        // layer-1 scatter sum
__device__ float g_out2[(size_t)Nn * Hh];        // layer-2 scatter sum
__device__ float g_rsq_out[Rr * Nn];
__device__ float g_rsq_in [Rr * Nn];
__device__ float g_pool[Gg * Hh];
__device__ float g_cnt [Gg];
__device__ uint32_t g_wtp   [2 * Rr * WSZ];      // [l][r][plane][n][ku] bf16x2
__device__ uint32_t g_wtp_in[WSZ_IN];            // [plane][n][ku]
__device__ float g_bsum [2 * Hh];                // per-layer sum of relation biases

// ---------------- helpers ----------------------------------------------------
__device__ __forceinline__ uint32_t packbf_hi(float a, float b, float& ra, float& rb) {
    __nv_bfloat162 h = __floats2bfloat162_rn(a, b);
    ra = a - __bfloat162float(h.x);
    rb = b - __bfloat162float(h.y);
    return *reinterpret_cast<uint32_t*>(&h);
}
__device__ __forceinline__ uint32_t packbf(float a, float b) {
    __nv_bfloat162 h = __floats2bfloat162_rn(a, b);
    return *reinterpret_cast<uint32_t*>(&h);
}

// ---------------- zero kernel (two ranges) -----------------------------------
__global__ void zero2_kernel(float4* a, int na4, float4* b, int nb4) {
    int i = blockIdx.x * blockDim.x + threadIdx.x;
    if (i < na4) a[i] = make_float4(0.f, 0.f, 0.f, 0.f);
    else if (i - na4 < nb4) b[i - na4] = make_float4(0.f, 0.f, 0.f, 0.f);
}

// ---------------- degrees ----------------------------------------------------
__global__ void degree_kernel(const int* __restrict__ src, const int* __restrict__ dst) {
    int i = blockIdx.x * blockDim.x + threadIdx.x;
    if (i < Rr * Ee) {
        int r = i / Ee;
        atomicAdd(&g_rsq_out[r * Nn + src[i]], 1.f);
        atomicAdd(&g_rsq_in [r * Nn + dst[i]], 1.f);
    }
}
__global__ void rsq_kernel() {
    int i = blockIdx.x * blockDim.x + threadIdx.x;
    if (i < Rr * Nn) {
        g_rsq_out[i] = rsqrtf(fmaxf(g_rsq_out[i], 1.f));
        g_rsq_in [i] = rsqrtf(fmaxf(g_rsq_in [i], 1.f));
    }
}

// ---------------- weight prep: bf16 hi/lo packed planes ----------------------
// layer weights: Wt[n][k] = W[r][k][n]; packed along k pairs.
__global__ void wprep_kernel(const float* __restrict__ W1,
                             const float* __restrict__ W2,
                             const float* __restrict__ Win) {
    int i = blockIdx.x * blockDim.x + threadIdx.x;
    const int TL = 2 * Rr * Hh * 64;   // 65536 packed elems for layer weights
    if (i < TL) {
        int lw = i >> 13;              // /(128*64)
        int rem = i & 8191;
        int n = rem >> 6, ku = rem & 63;
        int l = lw >> 2, r = lw & 3;
        const float* W = (l == 0 ? W1 : W2) + (size_t)r * Hh * Hh;
        float w0 = W[(2 * ku) * Hh + n];
        float w1 = W[(2 * ku + 1) * Hh + n];
        float r0, r1;
        uint32_t hi = packbf_hi(w0, w1, r0, r1);
        size_t base = (size_t)lw * WSZ;
        g_wtp[base + n * 64 + ku] = hi;
        g_wtp[base + Hh * 64 + n * 64 + ku] = packbf(r0, r1);
    } else {
        int j = i - TL;
        if (j < Hh * 32) {
            int n = j >> 5, ku = j & 31;
            float w0 = Win[(2 * ku) * Hh + n];
            float w1 = Win[(2 * ku + 1) * Hh + n];
            float r0, r1;
            uint32_t hi = packbf_hi(w0, w1, r0, r1);
            g_wtp_in[n * 32 + ku] = hi;
            g_wtp_in[Hh * 32 + n * 32 + ku] = packbf(r0, r1);
        }
    }
}

__global__ void bsum_kernel(const float* __restrict__ b1,
                            const float* __restrict__ b2) {
    int j = threadIdx.x;
    if (j < Hh) {
        float s1 = 0.f, s2 = 0.f;
        for (int r = 0; r < Rr; ++r) { s1 += b1[r * Hh + j]; s2 += b2[r * Hh + j]; }
        g_bsum[j] = s1; g_bsum[Hh + j] = s2;
    }
}

// ---------------- edge scatter (batched over relations) ----------------------
// out[d] += Y[r][s] * rso[r][s] * rsi[r][d]
__device__ __forceinline__ void red_add_v4(float* p, float4 v) {
    asm volatile(
        "{\n\t.reg .u64 pg;\n\t"
        "cvta.to.global.u64 pg, %0;\n\t"
        "red.global.add.v4.f32 [pg], {%1,%2,%3,%4};\n\t}"
        :: "l"(p), "f"(v.x), "f"(v.y), "f"(v.z), "f"(v.w) : "memory");
}

__global__ void scatter_kernel(const float* __restrict__ Y,
                               const int*   __restrict__ src,
                               const int*   __restrict__ dst,
                               const float* __restrict__ rso,
                               const float* __restrict__ rsi,
                               float*       __restrict__ out) {
    int r = blockIdx.y;
    int t = blockIdx.x * blockDim.x + threadIdx.x;
    int e = t >> 5;
    int lane = t & 31;
    if (e >= Ee) return;
    const int* srcr = src + (size_t)r * Ee;
    const int* dstr = dst + (size_t)r * Ee;
    int s = __ldg(&srcr[e]);
    int d = __ldg(&dstr[e]);
    float sc = __ldg(&rso[r * Nn + s]) * __ldg(&rsi[r * Nn + d]);
    const float* Yr = Y + (size_t)r * Nn * Hh;
    float4 v = *(const float4*)&Yr[(size_t)s * Hh + lane * 4];
    v.x *= sc; v.y *= sc; v.z *= sc; v.w *= sc;
    red_add_v4(&out[(size_t)d * Hh + lane * 4], v);
}

// ---------------- bf16 3-pass GEMM (m16n8k16) --------------------------------
// C[r][row,128] = relu?( A' @ (W_hi + W_lo)^T + cbias ),  A' = raw or relu(A+abias)
// Emulation: A_hi*W_hi + A_lo*W_hi + A_hi*W_lo; lo*lo term ~2^-16 neglected.
// Tile 128x128, chunk = 64 k (32 bf16x2 units), 3 passes x 4 k16-steps per chunk.
// smem: 4 tiles [128][36] u32 (A_hi, A_lo, B_hi, B_lo) = 73728 B, single buffer.
#define SMS 36
#define TILE_U (128 * SMS)

__device__ __forceinline__ void mma16(float* c, const uint32_t* a,
                                      uint32_t b0, uint32_t b1) {
    asm volatile(
        "mma.sync.aligned.m16n8k16.row.col.f32.bf16.bf16.f32 "
        "{%0,%1,%2,%3}, {%4,%5,%6,%7}, {%8,%9}, {%0,%1,%2,%3};"
        : "+f"(c[0]), "+f"(c[1]), "+f"(c[2]), "+f"(c[3])
        : "r"(a[0]), "r"(a[1]), "r"(a[2]), "r"(a[3]), "r"(b0), "r"(b1));
}

template <int AMODE>   // 0: raw A; 1: relu(A + abias[k])
__global__ void __launch_bounds__(256)
bf16_gemm_kernel(const float* __restrict__ A, int K,
                 const uint32_t* __restrict__ Wp, size_t wstride,   // u32 units
                 const float* __restrict__ abias,
                 const float* __restrict__ cbias,
                 float* __restrict__ C, size_t cstride,             // floats
                 int n, int relu_out) {
    extern __shared__ uint32_t smu[];
    uint32_t* tAhi = smu;
    uint32_t* tAlo = smu + TILE_U;
    uint32_t* tBhi = smu + 2 * TILE_U;
    uint32_t* tBlo = smu + 3 * TILE_U;

    const int tid = threadIdx.x;
    const int lane = tid & 31, warp = tid >> 5;
    const int wm = warp >> 1, wn = warp & 1;
    const int g = lane >> 2, t = lane & 3;
    const int row0 = blockIdx.x * 128;
    const uint32_t* Wr = Wp + (size_t)blockIdx.y * wstride;
    float* Cr = C + (size_t)blockIdx.y * cstride;

    const int KU = K >> 1;
    const int iters = KU >> 5;

    const int sr = tid >> 1;
    const int sc = (tid & 1) * 16;
    const int grow_s = row0 + sr;

    float acc[2][8][4];
#pragma unroll
    for (int mf = 0; mf < 2; ++mf)
#pragma unroll
        for (int nf = 0; nf < 8; ++nf)
#pragma unroll
            for (int q = 0; q < 4; ++q) acc[mf][nf][q] = 0.f;

    for (int ci = 0; ci < iters; ++ci) {
        if (ci) __syncthreads();
        // ---- stage chunk ci: A fp32 -> (hi,lo) planes; W planes direct
        {
            const int uc = ci * 32 + sc;
            const int k0 = 2 * uc;
            float v[32];
#pragma unroll
            for (int q = 0; q < 8; ++q) {
                float4 f = make_float4(0.f, 0.f, 0.f, 0.f);
                if (grow_s < n) {
                    f = *(const float4*)(A + (size_t)grow_s * K + k0 + q * 4);
                    if (AMODE == 1) {
                        float4 bb = *(const float4*)(abias + k0 + q * 4);
                        f.x = fmaxf(f.x + bb.x, 0.f);
                        f.y = fmaxf(f.y + bb.y, 0.f);
                        f.z = fmaxf(f.z + bb.z, 0.f);
                        f.w = fmaxf(f.w + bb.w, 0.f);
                    }
                }
                v[q * 4 + 0] = f.x; v[q * 4 + 1] = f.y;
                v[q * 4 + 2] = f.z; v[q * 4 + 3] = f.w;
            }
            uint32_t ha[16], la[16], wh[16], wl[16];
#pragma unroll
            for (int q = 0; q < 16; ++q) {
                float r0, r1;
                ha[q] = packbf_hi(v[2 * q], v[2 * q + 1], r0, r1);
                la[q] = packbf(r0, r1);
            }
            const uint32_t* whp = Wr + (size_t)sr * KU + uc;
            const uint32_t* wlp = whp + (size_t)Hh * KU;
#pragma unroll
            for (int q = 0; q < 4; ++q) {
                *(uint4*)&wh[q * 4] = *(const uint4*)(whp + q * 4);
                *(uint4*)&wl[q * 4] = *(const uint4*)(wlp + q * 4);
            }
            uint32_t* d0 = tAhi + sr * SMS + sc;
            uint32_t* d1 = tAlo + sr * SMS + sc;
            uint32_t* d2 = tBhi + sr * SMS + sc;
            uint32_t* d3 = tBlo + sr * SMS + sc;
#pragma unroll
            for (int q = 0; q < 4; ++q) {
                *(uint4*)(d0 + q * 4) = *(uint4*)&ha[q * 4];
                *(uint4*)(d1 + q * 4) = *(uint4*)&la[q * 4];
                *(uint4*)(d2 + q * 4) = *(uint4*)&wh[q * 4];
                *(uint4*)(d3 + q * 4) = *(uint4*)&wl[q * 4];
            }
        }
        __syncthreads();

        // ---- 3 passes x 4 k16-steps
#pragma unroll
        for (int ks = 0; ks < 12; ++ks) {
            const int p = ks >> 2;
            const int kk = (ks & 3) * 8;
            const uint32_t* at = (p == 1) ? tAlo : tAhi;
            const uint32_t* bt = (p == 2) ? tBlo : tBhi;
            uint32_t a[2][4];
#pragma unroll
            for (int mf = 0; mf < 2; ++mf) {
                int r_ = wm * 32 + mf * 16 + g;
                a[mf][0] = at[(r_    ) * SMS + kk + t    ];
                a[mf][1] = at[(r_ + 8) * SMS + kk + t    ];
                a[mf][2] = at[(r_    ) * SMS + kk + t + 4];
                a[mf][3] = at[(r_ + 8) * SMS + kk + t + 4];
            }
#pragma unroll
            for (int nf = 0; nf < 8; ++nf) {
                int nr = wn * 64 + nf * 8 + g;
                uint32_t b0 = bt[nr * SMS + kk + t];
                uint32_t b1 = bt[nr * SMS + kk + t + 4];
                mma16(acc[0][nf], a[0], b0, b1);
                mma16(acc[1][nf], a[1], b0, b1);
            }
        }
    }

    // ---- epilogue
#pragma unroll
    for (int mf = 0; mf < 2; ++mf) {
#pragma unroll
        for (int half = 0; half < 2; ++half) {
            int grow = row0 + wm * 32 + mf * 16 + g + half * 8;
            if (grow >= n) continue;
            float* crow = Cr + (size_t)grow * 128;
#pragma unroll
            for (int nf = 0; nf < 8; ++nf) {
                int col = wn * 64 + nf * 8 + 2 * t;
                float v0 = acc[mf][nf][half * 2 + 0];
                float v1 = acc[mf][nf][half * 2 + 1];
                if (cbias) { v0 += cbias[col]; v1 += cbias[col + 1]; }
                if (relu_out) { v0 = fmaxf(v0, 0.f); v1 = fmaxf(v1, 0.f); }
                float2 v; v.x = v0; v.y = v1;
                *(float2*)(crow + col) = v;
            }
        }
    }
}

// ---------------- pooling ----------------------------------------------------
__global__ void count_kernel(const int* __restrict__ gid) {
    int i = blockIdx.x * blockDim.x + threadIdx.x;
    if (i < Nn) atomicAdd(&g_cnt[gid[i]], 1.f);
}
__global__ void pool_kernel(const float* __restrict__ h, const int* __restrict__ gid) {
    int t = blockIdx.x * blockDim.x + threadIdx.x;
    int node = t >> 5;
    int lane = t & 31;
    if (node >= Nn) return;
    int g = __ldg(&gid[node]);
    float4 v = *(const float4*)&h[(size_t)node * Hh + lane * 4];
    red_add_v4(&g_pool[g * Hh + lane * 4], v);
}

// ---------------- MLP head (single block) -------------------------------------
__global__ void mlp_kernel(const float* __restrict__ Wm1, const float* __restrict__ bm1,
                           const float* __restrict__ Wm2, const float* __restrict__ bm2,
                           const float* __restrict__ Wm3, const float* __restrict__ bm3,
                           float* __restrict__ out) {
    __shared__ float z[Gg * Hh];
    int tid = threadIdx.x;   // 256
    for (int i = tid; i < Gg * Hh; i += 256)
        z[i] = g_pool[i] / fmaxf(g_cnt[i >> 7], 1.f) + g_bsum[Hh + (i & 127)];
    __syncthreads();
    float r1[32];
#pragma unroll
    for (int t = 0; t < 32; ++t) {
        int o = tid + t * 256, g = o >> 7, j = o & 127;
        float s = bm1[j];
        for (int k = 0; k < Hh; ++k) s += z[(g << 7) + k] * Wm1[k * Hh + j];
        r1[t] = fmaxf(s, 0.f);
    }
    __syncthreads();
#pragma unroll
    for (int t = 0; t < 32; ++t) z[tid + t * 256] = r1[t];
    __syncthreads();
#pragma unroll
    for (int t = 0; t < 32; ++t) {
        int o = tid + t * 256, g = o >> 7, j = o & 127;
        float s = bm2[j];
        for (int k = 0; k < Hh; ++k) s += z[(g << 7) + k] * Wm2[k * Hh + j];
        r1[t] = fmaxf(s, 0.f);
    }
    __syncthreads();
#pragma unroll
    for (int t = 0; t < 32; ++t) z[tid + t * 256] = r1[t];
    __syncthreads();
    if (tid < Gg * Cc) {
        int g = tid >> 1, c = tid & 1;
        float s = bm3[c];
        for (int k = 0; k < Hh; ++k) s += z[(g << 7) + k] * Wm3[k * Cc + c];
        out[tid] = s;
    }
}

// ---------------- launch -------------------------------------------------------
static void* symv(const void* s) {
    void* p = nullptr;
    cudaGetSymbolAddress(&p, s);
    return p;
}

extern "C" void kernel_launch(void* const* d_in, const int* in_sizes, int n_in,
                              void* d_out, int out_size) {
    const float* x    = (const float*)d_in[0];
    const int*   src  = (const int*)  d_in[1];
    const int*   dst  = (const int*)  d_in[2];
    const int*   gid  = (const int*)  d_in[3];
    const float* W_in = (const float*)d_in[4];
    const float* b_in = (const float*)d_in[5];
    const float* W1   = (const float*)d_in[6];
    const float* b1   = (const float*)d_in[7];
    const float* W2   = (const float*)d_in[8];
    const float* b2   = (const float*)d_in[9];
    const float* Wm1  = (const float*)d_in[10];
    const float* bm1  = (const float*)d_in[11];
    const float* Wm2  = (const float*)d_in[12];
    const float* bm2  = (const float*)d_in[13];
    const float* Wm3  = (const float*)d_in[14];
    const float* bm3  = (const float*)d_in[15];
    float* out = (float*)d_out;

    float*    p_h0   = (float*)   symv(g_h0);
    float*    p_Y    = (float*)   symv(g_Y);
    float*    p_out1 = (float*)   symv(g_out1);
    float*    p_out2 = (float*)   symv(g_out2);
    float*    p_rso  = (float*)   symv(g_rsq_out);
    float*    p_rsi  = (float*)   symv(g_rsq_in);
    float*    p_pool = (float*)   symv(g_pool);
    float*    p_cnt  = (float*)   symv(g_cnt);
    uint32_t* p_wtp  = (uint32_t*)symv(g_wtp);
    uint32_t* p_wtin = (uint32_t*)symv(g_wtp_in);
    float*    p_bsum = (float*)   symv(g_bsum);

    const int TB = 256;
    const int gemm_blocks = (Nn + 127) / 128;       // 782
    const int scat_blocks = (Ee * 32 + TB - 1) / TB;
    const int smem_gemm = 4 * TILE_U * 4;           // 73728 bytes

    cudaFuncSetAttribute(bf16_gemm_kernel<0>,
                         cudaFuncAttributeMaxDynamicSharedMemorySize, smem_gemm);
    cudaFuncSetAttribute(bf16_gemm_kernel<1>,
                         cudaFuncAttributeMaxDynamicSharedMemorySize, smem_gemm);

    const int RN4 = Rr * Nn / 4;
    const int NH4 = Nn * Hh / 4;

    // 0: zero degrees
    zero2_kernel<<<(2 * RN4 + TB - 1) / TB, TB>>>((float4*)p_rso, RN4,
                                                  (float4*)p_rsi, RN4);
    // 1-2: degrees -> rsqrt
    degree_kernel<<<(Rr * Ee + TB - 1) / TB, TB>>>(src, dst);
    rsq_kernel<<<(Rr * Nn + TB - 1) / TB, TB>>>();
    // 3: weight prep (bf16 hi/lo packed, transposed)
    wprep_kernel<<<(2 * Rr * Hh * 64 + Hh * 32 + TB - 1) / TB, TB>>>(W1, W2, W_in);
    // 4: h0 = relu(x @ W_in + b_in)
    bf16_gemm_kernel<0><<<dim3(gemm_blocks, 1), 256, smem_gemm>>>(
        x, INF, p_wtin, 0, nullptr, b_in, p_h0, 0, Nn, 1);
    // 5: layer-1 GEMMs, all relations  (<-- ncu -s 5 -c 1 capture slot)
    bf16_gemm_kernel<0><<<dim3(gemm_blocks, Rr), 256, smem_gemm>>>(
        p_h0, Hh, p_wtp, WSZ, nullptr, nullptr, p_Y, (size_t)Nn * Hh, Nn, 0);
    // 6: bias sums (needed by layer-2 GEMM + mlp)
    bsum_kernel<<<1, 128>>>(b1, b2);
    // 7: zero scatter outputs
    zero2_kernel<<<(2 * NH4 + TB - 1) / TB, TB>>>((float4*)p_out1, NH4,
                                                  (float4*)p_out2, NH4);
    // 8: layer-1 scatter, all relations
    scatter_kernel<<<dim3(scat_blocks, Rr), TB>>>(p_Y, src, dst, p_rso, p_rsi, p_out1);
    // 9: layer-2 GEMMs (relu(out1 + bsum1) fused into A-load)
    bf16_gemm_kernel<1><<<dim3(gemm_blocks, Rr), 256, smem_gemm>>>(
        p_out1, Hh, p_wtp + (size_t)Rr * WSZ, WSZ, p_bsum, nullptr,
        p_Y, (size_t)Nn * Hh, Nn, 0);
    // 10: zero pool buffers
    zero2_kernel<<<(Gg * Hh / 4 + Gg / 4 + TB - 1) / TB, TB>>>(
        (float4*)p_pool, Gg * Hh / 4, (float4*)p_cnt, Gg / 4);
    // 11: layer-2 scatter
    scatter_kernel<<<dim3(scat_blocks, Rr), TB>>>(p_Y, src, dst, p_rso, p_rsi, p_out2);
    // 12-13: per-graph mean pool
    count_kernel<<<(Nn + TB - 1) / TB, TB>>>(gid);
    pool_kernel<<<(Nn * 32 + TB - 1) / TB, TB>>>(p_out2, gid);
    // 14: MLP head
    mlp_kernel<<<1, TB>>>(Wm1, bm1, Wm2, bm2, Wm3, bm3, out);
}

// round 8
// speedup vs baseline: 1.7815x; 1.0486x over previous
#include <cuda_runtime.h>
#include <cuda_bf16.h>
#include <math.h>
#include <stdint.h>

// Problem constants (fixed by the reference)
#define Nn 100000
#define Ee 400000
#define Rr 4
#define Gg 64
#define INF 64
#define Hh 128
#define Cc 2

#define WSZ    (2 * Hh * 64)   // u32 per relation weight (hi+lo planes, KU=64)
#define WSZ_IN (2 * Hh * 32)   // input weight (KU=32)

// ---------------- scratch (device globals; no allocation allowed) ----------
__device__ float g_Y   [(size_t)Rr * Nn * Hh];   // per-relation GEMM outputs
__device__ float g_out1[(size_t)Nn * Hh];        // layer-1 scatter sum
__device__ float g_out2[(size_t)Nn * Hh];        // layer-2 scatter sum
__device__ float g_rsq_out[Rr * Nn];
__device__ float g_rsq_in [Rr * Nn];
__device__ float g_pool[Gg * Hh];
__device__ float g_cnt [Gg];
__device__ uint32_t g_wtp   [2 * Rr * WSZ];      // [l][r][plane][n][ku] bf16x2
__device__ uint32_t g_wtp_in[WSZ_IN];            // [plane][n][ku]
__device__ float g_bsum [2 * Hh];
// A-operand bf16x2 planes (two sets, ping-pong)
__device__ uint32_t g_pa_h[(size_t)Nn * 64];
__device__ uint32_t g_pa_l[(size_t)Nn * 64];
__device__ uint32_t g_pb_h[(size_t)Nn * 64];
__device__ uint32_t g_pb_l[(size_t)Nn * 64];

// ---------------- helpers ----------------------------------------------------
__device__ __forceinline__ uint32_t packbf_hi(float a, float b, float& ra, float& rb) {
    __nv_bfloat162 h = __floats2bfloat162_rn(a, b);
    ra = a - __bfloat162float(h.x);
    rb = b - __bfloat162float(h.y);
    return *reinterpret_cast<uint32_t*>(&h);
}
__device__ __forceinline__ uint32_t packbf(float a, float b) {
    __nv_bfloat162 h = __floats2bfloat162_rn(a, b);
    return *reinterpret_cast<uint32_t*>(&h);
}

// ---------------- zero kernel (two ranges) -----------------------------------
__global__ void zero2_kernel(float4* a, int na4, float4* b, int nb4) {
    int i = blockIdx.x * blockDim.x + threadIdx.x;
    if (i < na4) a[i] = make_float4(0.f, 0.f, 0.f, 0.f);
    else if (i - na4 < nb4) b[i - na4] = make_float4(0.f, 0.f, 0.f, 0.f);
}

// ---------------- degrees ----------------------------------------------------
__global__ void degree_kernel(const int* __restrict__ src, const int* __restrict__ dst) {
    int i = blockIdx.x * blockDim.x + threadIdx.x;
    if (i < Rr * Ee) {
        int r = i / Ee;
        atomicAdd(&g_rsq_out[r * Nn + src[i]], 1.f);
        atomicAdd(&g_rsq_in [r * Nn + dst[i]], 1.f);
    }
}
__global__ void rsq_kernel() {
    int i = blockIdx.x * blockDim.x + threadIdx.x;
    if (i < Rr * Nn) {
        g_rsq_out[i] = rsqrtf(fmaxf(g_rsq_out[i], 1.f));
        g_rsq_in [i] = rsqrtf(fmaxf(g_rsq_in [i], 1.f));
    }
}

// ---------------- weight prep: bf16 hi/lo packed planes ----------------------
__global__ void wprep_kernel(const float* __restrict__ W1,
                             const float* __restrict__ W2,
                             const float* __restrict__ Win) {
    int i = blockIdx.x * blockDim.x + threadIdx.x;
    const int TL = 2 * Rr * Hh * 64;   // 65536
    if (i < TL) {
        int lw = i >> 13;
        int rem = i & 8191;
        int n = rem >> 6, ku = rem & 63;
        int l = lw >> 2, r = lw & 3;
        const float* W = (l == 0 ? W1 : W2) + (size_t)r * Hh * Hh;
        float w0 = W[(2 * ku) * Hh + n];
        float w1 = W[(2 * ku + 1) * Hh + n];
        float r0, r1;
        uint32_t hi = packbf_hi(w0, w1, r0, r1);
        size_t base = (size_t)lw * WSZ;
        g_wtp[base + n * 64 + ku] = hi;
        g_wtp[base + Hh * 64 + n * 64 + ku] = packbf(r0, r1);
    } else {
        int j = i - TL;
        if (j < Hh * 32) {
            int n = j >> 5, ku = j & 31;
            float w0 = Win[(2 * ku) * Hh + n];
            float w1 = Win[(2 * ku + 1) * Hh + n];
            float r0, r1;
            uint32_t hi = packbf_hi(w0, w1, r0, r1);
            g_wtp_in[n * 32 + ku] = hi;
            g_wtp_in[Hh * 32 + n * 32 + ku] = packbf(r0, r1);
        }
    }
}

__global__ void bsum_kernel(const float* __restrict__ b1,
                            const float* __restrict__ b2) {
    int j = threadIdx.x;
    if (j < Hh) {
        float s1 = 0.f, s2 = 0.f;
        for (int r = 0; r < Rr; ++r) { s1 += b1[r * Hh + j]; s2 += b2[r * Hh + j]; }
        g_bsum[j] = s1; g_bsum[Hh + j] = s2;
    }
}

// ---------------- fp32 -> bf16 hi/lo plane conversion -------------------------
// src has rows of 2*KU2 floats; optional bias[2*KU2] add + relu.
__global__ void conv_kernel(const float* __restrict__ src, int KU2,
                            const float* __restrict__ bias, int relu,
                            uint32_t* __restrict__ ph, uint32_t* __restrict__ pl,
                            int total) {
    int i = blockIdx.x * blockDim.x + threadIdx.x;
    if (i >= total) return;
    int row = i / KU2, ku = i - row * KU2;
    float2 f = *(const float2*)(src + (size_t)row * (2 * KU2) + 2 * ku);
    if (bias) { f.x += bias[2 * ku]; f.y += bias[2 * ku + 1]; }
    if (relu) { f.x = fmaxf(f.x, 0.f); f.y = fmaxf(f.y, 0.f); }
    float r0, r1;
    ph[i] = packbf_hi(f.x, f.y, r0, r1);
    pl[i] = packbf(r0, r1);
}

// ---------------- edge scatter (batched over relations) ----------------------
__device__ __forceinline__ void red_add_v4(float* p, float4 v) {
    asm volatile(
        "{\n\t.reg .u64 pg;\n\t"
        "cvta.to.global.u64 pg, %0;\n\t"
        "red.global.add.v4.f32 [pg], {%1,%2,%3,%4};\n\t}"
        :: "l"(p), "f"(v.x), "f"(v.y), "f"(v.z), "f"(v.w) : "memory");
}

__global__ void scatter_kernel(const float* __restrict__ Y,
                               const int*   __restrict__ src,
                               const int*   __restrict__ dst,
                               const float* __restrict__ rso,
                               const float* __restrict__ rsi,
                               float*       __restrict__ out) {
    int r = blockIdx.y;
    int t = blockIdx.x * blockDim.x + threadIdx.x;
    int e = t >> 5;
    int lane = t & 31;
    if (e >= Ee) return;
    const int* srcr = src + (size_t)r * Ee;
    const int* dstr = dst + (size_t)r * Ee;
    int s = __ldg(&srcr[e]);
    int d = __ldg(&dstr[e]);
    float sc = __ldg(&rso[r * Nn + s]) * __ldg(&rsi[r * Nn + d]);
    const float* Yr = Y + (size_t)r * Nn * Hh;
    float4 v = *(const float4*)&Yr[(size_t)s * Hh + lane * 4];
    v.x *= sc; v.y *= sc; v.z *= sc; v.w *= sc;
    red_add_v4(&out[(size_t)d * Hh + lane * 4], v);
}

// ---------------- bf16 3-pass GEMM (m16n8k16), plane A, cp.async -------------
// C = A @ (W_hi + W_lo)^T with A pre-split into bf16x2 hi/lo planes.
// Passes: Ahi*Whi + Alo*Whi + Ahi*Wlo (lo*lo ~2^-16 dropped).
// Tiles [128][36] u32 x4 planes x2 buffers = 147456 B smem. BK chunk = 32 u32.
#define SMS 36
#define TILE_U (128 * SMS)

__device__ __forceinline__ void mma16(float* c, const uint32_t* a,
                                      uint32_t b0, uint32_t b1) {
    asm volatile(
        "mma.sync.aligned.m16n8k16.row.col.f32.bf16.bf16.f32 "
        "{%0,%1,%2,%3}, {%4,%5,%6,%7}, {%8,%9}, {%0,%1,%2,%3};"
        : "+f"(c[0]), "+f"(c[1]), "+f"(c[2]), "+f"(c[3])
        : "r"(a[0]), "r"(a[1]), "r"(a[2]), "r"(a[3]), "r"(b0), "r"(b1));
}

__device__ __forceinline__ void cpa16(uint32_t daddr, const uint32_t* src, uint32_t nbytes) {
    asm volatile("cp.async.cg.shared.global [%0], [%1], 16, %2;"
                 :: "r"(daddr), "l"(src), "r"(nbytes) : "memory");
}

template <int COUT>   // 0: fp32 C[n,128]; 1: bf16x2 plane out (bias+relu+pack)
__global__ void __launch_bounds__(256)
bf16_gemm_kernel(const uint32_t* __restrict__ Ah, const uint32_t* __restrict__ Al,
                 int KU,                                          // 32 or 64
                 const uint32_t* __restrict__ Wp, size_t wstride, // u32
                 const float* __restrict__ cbias,                 // nullable
                 float* __restrict__ C, size_t cstride,           // COUT=0
                 uint32_t* __restrict__ Ph, uint32_t* __restrict__ Pl, // COUT=1
                 int n) {
    extern __shared__ uint32_t smu[];

    const int tid = threadIdx.x;
    const int lane = tid & 31, warp = tid >> 5;
    const int wm = warp >> 1, wn = warp & 1;
    const int g = lane >> 2, t = lane & 3;
    const int row0 = blockIdx.x * 128;
    const uint32_t* Wr = Wp + (size_t)blockIdx.y * wstride;
    const int iters = KU >> 5;

    const int sr = tid >> 1;
    const int sc = (tid & 1) * 16;
    const int grow_s = row0 + sr;
    const int arow = (grow_s < n) ? grow_s : (n - 1);
    const uint32_t avalid = (grow_s < n) ? 16u : 0u;

    uint32_t smbase;
    {
        uint64_t b64 = __cvta_generic_to_shared(smu);
        smbase = (uint32_t)b64;
    }

    float acc[2][8][4];
#pragma unroll
    for (int mf = 0; mf < 2; ++mf)
#pragma unroll
        for (int nf = 0; nf < 8; ++nf)
#pragma unroll
            for (int q = 0; q < 4; ++q) acc[mf][nf][q] = 0.f;

    // ---- issue async stages for all chunks (max 2)
#pragma unroll
    for (int ci = 0; ci < 2; ++ci) {
        if (ci >= iters) break;
        const int uc = ci * 32 + sc;
        const uint32_t dbase = smbase + (ci & 1) * (4 * TILE_U * 4);
        const uint32_t doff = (sr * SMS + sc) * 4;
        const uint32_t* pAh = Ah + (size_t)arow * KU + uc;
        const uint32_t* pAl = Al + (size_t)arow * KU + uc;
        const uint32_t* pWh = Wr + (size_t)sr * KU + uc;
        const uint32_t* pWl = pWh + (size_t)Hh * KU;
#pragma unroll
        for (int q = 0; q < 4; ++q) {
            cpa16(dbase + doff + q * 16,                    pAh + q * 4, avalid);
            cpa16(dbase + TILE_U * 4 + doff + q * 16,       pAl + q * 4, avalid);
            cpa16(dbase + 2 * TILE_U * 4 + doff + q * 16,   pWh + q * 4, 16u);
            cpa16(dbase + 3 * TILE_U * 4 + doff + q * 16,   pWl + q * 4, 16u);
        }
        asm volatile("cp.async.commit_group;" ::: "memory");
    }

    for (int ci = 0; ci < iters; ++ci) {
        if (ci + 1 < iters)
            asm volatile("cp.async.wait_group 1;" ::: "memory");
        else
            asm volatile("cp.async.wait_group 0;" ::: "memory");
        __syncthreads();

        const uint32_t* base = smu + (ci & 1) * (4 * TILE_U);
#pragma unroll
        for (int ks = 0; ks < 12; ++ks) {
            const int p = ks >> 2;
            const int kk = (ks & 3) * 8;
            const uint32_t* at = base + ((p == 1) ? TILE_U : 0);
            const uint32_t* bt = base + 2 * TILE_U + ((p == 2) ? TILE_U : 0);
            uint32_t a[2][4];
#pragma unroll
            for (int mf = 0; mf < 2; ++mf) {
                int r_ = wm * 32 + mf * 16 + g;
                a[mf][0] = at[(r_    ) * SMS + kk + t    ];
                a[mf][1] = at[(r_ + 8) * SMS + kk + t    ];
                a[mf][2] = at[(r_    ) * SMS + kk + t + 4];
                a[mf][3] = at[(r_ + 8) * SMS + kk + t + 4];
            }
#pragma unroll
            for (int nf = 0; nf < 8; ++nf) {
                int nr = wn * 64 + nf * 8 + g;
                uint32_t b0 = bt[nr * SMS + kk + t];
                uint32_t b1 = bt[nr * SMS + kk + t + 4];
                mma16(acc[0][nf], a[0], b0, b1);
                mma16(acc[1][nf], a[1], b0, b1);
            }
        }
        if (ci + 1 < iters) __syncthreads();
    }

    // ---- epilogue
#pragma unroll
    for (int mf = 0; mf < 2; ++mf) {
#pragma unroll
        for (int half = 0; half < 2; ++half) {
            int grow = row0 + wm * 32 + mf * 16 + g + half * 8;
            if (grow >= n) continue;
#pragma unroll
            for (int nf = 0; nf < 8; ++nf) {
                int col = wn * 64 + nf * 8 + 2 * t;
                float v0 = acc[mf][nf][half * 2 + 0];
                float v1 = acc[mf][nf][half * 2 + 1];
                if (COUT == 0) {
                    float2 v; v.x = v0; v.y = v1;
                    *(float2*)(C + (size_t)blockIdx.y * cstride
                               + (size_t)grow * 128 + col) = v;
                } else {
                    v0 = fmaxf(v0 + cbias[col], 0.f);
                    v1 = fmaxf(v1 + cbias[col + 1], 0.f);
                    float r0, r1;
                    uint32_t hi = packbf_hi(v0, v1, r0, r1);
                    size_t idx = (size_t)grow * 64 + (col >> 1);
                    Ph[idx] = hi;
                    Pl[idx] = packbf(r0, r1);
                }
            }
        }
    }
}

// ---------------- pooling ----------------------------------------------------
__global__ void count_kernel(const int* __restrict__ gid) {
    int i = blockIdx.x * blockDim.x + threadIdx.x;
    if (i < Nn) atomicAdd(&g_cnt[gid[i]], 1.f);
}
__global__ void pool_kernel(const float* __restrict__ h, const int* __restrict__ gid) {
    int t = blockIdx.x * blockDim.x + threadIdx.x;
    int node = t >> 5;
    int lane = t & 31;
    if (node >= Nn) return;
    int g = __ldg(&gid[node]);
    float4 v = *(const float4*)&h[(size_t)node * Hh + lane * 4];
    red_add_v4(&g_pool[g * Hh + lane * 4], v);
}

// ---------------- MLP head (single block) -------------------------------------
__global__ void mlp_kernel(const float* __restrict__ Wm1, const float* __restrict__ bm1,
                           const float* __restrict__ Wm2, const float* __restrict__ bm2,
                           const float* __restrict__ Wm3, const float* __restrict__ bm3,
                           float* __restrict__ out) {
    __shared__ float z[Gg * Hh];
    int tid = threadIdx.x;   // 256
    for (int i = tid; i < Gg * Hh; i += 256)
        z[i] = g_pool[i] / fmaxf(g_cnt[i >> 7], 1.f) + g_bsum[Hh + (i & 127)];
    __syncthreads();
    float r1[32];
#pragma unroll
    for (int t = 0; t < 32; ++t) {
        int o = tid + t * 256, g = o >> 7, j = o & 127;
        float s = bm1[j];
        for (int k = 0; k < Hh; ++k) s += z[(g << 7) + k] * Wm1[k * Hh + j];
        r1[t] = fmaxf(s, 0.f);
    }
    __syncthreads();
#pragma unroll
    for (int t = 0; t < 32; ++t) z[tid + t * 256] = r1[t];
    __syncthreads();
#pragma unroll
    for (int t = 0; t < 32; ++t) {
        int o = tid + t * 256, g = o >> 7, j = o & 127;
        float s = bm2[j];
        for (int k = 0; k < Hh; ++k) s += z[(g << 7) + k] * Wm2[k * Hh + j];
        r1[t] = fmaxf(s, 0.f);
    }
    __syncthreads();
#pragma unroll
    for (int t = 0; t < 32; ++t) z[tid + t * 256] = r1[t];
    __syncthreads();
    if (tid < Gg * Cc) {
        int g = tid >> 1, c = tid & 1;
        float s = bm3[c];
        for (int k = 0; k < Hh; ++k) s += z[(g << 7) + k] * Wm3[k * Cc + c];
        out[tid] = s;
    }
}

// ---------------- launch -------------------------------------------------------
static void* symv(const void* s) {
    void* p = nullptr;
    cudaGetSymbolAddress(&p, s);
    return p;
}

extern "C" void kernel_launch(void* const* d_in, const int* in_sizes, int n_in,
                              void* d_out, int out_size) {
    const float* x    = (const float*)d_in[0];
    const int*   src  = (const int*)  d_in[1];
    const int*   dst  = (const int*)  d_in[2];
    const int*   gid  = (const int*)  d_in[3];
    const float* W_in = (const float*)d_in[4];
    const float* b_in = (const float*)d_in[5];
    const float* W1   = (const float*)d_in[6];
    const float* b1   = (const float*)d_in[7];
    const float* W2   = (const float*)d_in[8];
    const float* b2   = (const float*)d_in[9];
    const float* Wm1  = (const float*)d_in[10];
    const float* bm1  = (const float*)d_in[11];
    const float* Wm2  = (const float*)d_in[12];
    const float* bm2  = (const float*)d_in[13];
    const float* Wm3  = (const float*)d_in[14];
    const float* bm3  = (const float*)d_in[15];
    float* out = (float*)d_out;

    float*    p_Y    = (float*)   symv(g_Y);
    float*    p_out1 = (float*)   symv(g_out1);
    float*    p_out2 = (float*)   symv(g_out2);
    float*    p_rso  = (float*)   symv(g_rsq_out);
    float*    p_rsi  = (float*)   symv(g_rsq_in);
    float*    p_pool = (float*)   symv(g_pool);
    float*    p_cnt  = (float*)   symv(g_cnt);
    uint32_t* p_wtp  = (uint32_t*)symv(g_wtp);
    uint32_t* p_wtin = (uint32_t*)symv(g_wtp_in);
    float*    p_bsum = (float*)   symv(g_bsum);
    uint32_t* p_pah  = (uint32_t*)symv(g_pa_h);
    uint32_t* p_pal  = (uint32_t*)symv(g_pa_l);
    uint32_t* p_pbh  = (uint32_t*)symv(g_pb_h);
    uint32_t* p_pbl  = (uint32_t*)symv(g_pb_l);

    const int TB = 256;
    const int gemm_blocks = (Nn + 127) / 128;       // 782
    const int scat_blocks = (Ee * 32 + TB - 1) / TB;
    const int smem_gemm = 8 * TILE_U * 4;           // 147456 bytes

    cudaFuncSetAttribute(bf16_gemm_kernel<0>,
                         cudaFuncAttributeMaxDynamicSharedMemorySize, smem_gemm);
    cudaFuncSetAttribute(bf16_gemm_kernel<1>,
                         cudaFuncAttributeMaxDynamicSharedMemorySize, smem_gemm);

    const int RN4 = Rr * Nn / 4;
    const int NH4 = Nn * Hh / 4;

    // 0: weight prep
    wprep_kernel<<<(2 * Rr * Hh * 64 + Hh * 32 + TB - 1) / TB, TB>>>(W1, W2, W_in);
    // 1: x -> planes (setA, KU=32)
    conv_kernel<<<(Nn * 32 + TB - 1) / TB, TB>>>(x, 32, nullptr, 0, p_pah, p_pal, Nn * 32);
    // 2: input GEMM: h0 planes (setB) = relu(x@W_in + b_in), packed
    bf16_gemm_kernel<1><<<dim3(gemm_blocks, 1), 256, smem_gemm>>>(
        p_pah, p_pal, 32, p_wtin, 0, b_in, nullptr, 0, p_pbh, p_pbl, Nn);
    // 3: layer-1 GEMMs, all relations -> Y
    bf16_gemm_kernel<0><<<dim3(gemm_blocks, Rr), 256, smem_gemm>>>(
        p_pbh, p_pbl, 64, p_wtp, WSZ, nullptr, p_Y, (size_t)Nn * Hh, nullptr, nullptr, Nn);
    // 4: zero degree buffers
    zero2_kernel<<<(2 * RN4 + TB - 1) / TB, TB>>>((float4*)p_rso, RN4,
                                                  (float4*)p_rsi, RN4);
    // 5-6: degrees -> rsqrt
    degree_kernel<<<(Rr * Ee + TB - 1) / TB, TB>>>(src, dst);
    rsq_kernel<<<(Rr * Nn + TB - 1) / TB, TB>>>();
    // 7: bias sums
    bsum_kernel<<<1, 128>>>(b1, b2);
    // 8: zero scatter outputs
    zero2_kernel<<<(2 * NH4 + TB - 1) / TB, TB>>>((float4*)p_out1, NH4,
                                                  (float4*)p_out2, NH4);
    // 9: layer-1 scatter, all relations
    scatter_kernel<<<dim3(scat_blocks, Rr), TB>>>(p_Y, src, dst, p_rso, p_rsi, p_out1);
    // 10: relu(out1 + bsum1) -> planes (setA, KU=64)
    conv_kernel<<<(Nn * 64 + TB - 1) / TB, TB>>>(p_out1, 64, p_bsum, 1,
                                                 p_pah, p_pal, Nn * 64);
    // 11: layer-2 GEMMs -> Y
    bf16_gemm_kernel<0><<<dim3(gemm_blocks, Rr), 256, smem_gemm>>>(
        p_pah, p_pal, 64, p_wtp + (size_t)Rr * WSZ, WSZ, nullptr,
        p_Y, (size_t)Nn * Hh, nullptr, nullptr, Nn);
    // 12: zero pool buffers
    zero2_kernel<<<(Gg * Hh / 4 + Gg / 4 + TB - 1) / TB, TB>>>(
        (float4*)p_pool, Gg * Hh / 4, (float4*)p_cnt, Gg / 4);
    // 13: layer-2 scatter
    scatter_kernel<<<dim3(scat_blocks, Rr), TB>>>(p_Y, src, dst, p_rso, p_rsi, p_out2);
    // 14-15: per-graph mean pool
    count_kernel<<<(Nn + TB - 1) / TB, TB>>>(gid);
    pool_kernel<<<(Nn * 32 + TB - 1) / TB, TB>>>(p_out2, gid);
    // 16: MLP head
    mlp_kernel<<<1, TB>>>(Wm1, bm1, Wm2, bm2, Wm3, bm3, out);
}

// round 9
// speedup vs baseline: 2.3284x; 1.3070x over previous
#include <cuda_runtime.h>
#include <cuda_bf16.h>
#include <math.h>
#include <stdint.h>

// Problem constants (fixed by the reference)
#define Nn 100000
#define Ee 400000
#define Rr 4
#define Gg 64
#define INF 64
#define Hh 128
#define Cc 2
#define RN (Rr * Nn)        // 400000
#define RE (Rr * Ee)        // 1600000

#define KU_L 256            // stacked K for layer GEMMs (512 k / 2)
#define KU_I 32             // input GEMM (64 k / 2)
#define WST  (2 * Hh * KU_L)   // u32 per layer: hi+lo planes
#define WST_IN (2 * Hh * KU_I)

// ---------------- scratch (device globals; no allocation allowed) ----------
__device__ float    g_h   [(size_t)Nn * Hh];     // h0 then h1 (fp32)
__device__ float    g_out2[(size_t)Nn * Hh];     // layer-2 output (fp32)
__device__ float    g_rso [RN];                  // rsqrt(max(deg_out,1))
__device__ float    g_rsi [RN];
__device__ int      g_cout[RN];
__device__ int      g_cin [RN];                  // also reused as fill counter
__device__ int      g_rp  [RN + 1];              // CSR row_ptr (by dst)
__device__ int      g_bs  [512];                 // block sums for scan
__device__ int      g_eidx  [RE];                // CSR: src index
__device__ float    g_escale[RE];                // CSR: rso[src]
__device__ uint32_t g_wst   [2 * WST];           // stacked layer weights (bf16x2)
__device__ uint32_t g_wtin  [WST_IN];
__device__ float    g_bsum  [2 * Hh];
__device__ uint32_t g_Ah[(size_t)Nn * KU_L];     // A planes (hi)
__device__ uint32_t g_Al[(size_t)Nn * KU_L];     // A planes (lo)
__device__ float    g_pool[Gg * Hh];
__device__ float    g_cnt [Gg];

// ---------------- helpers ----------------------------------------------------
__device__ __forceinline__ uint32_t packbf_hi(float a, float b, float& ra, float& rb) {
    __nv_bfloat162 h = __floats2bfloat162_rn(a, b);
    ra = a - __bfloat162float(h.x);
    rb = b - __bfloat162float(h.y);
    return *reinterpret_cast<uint32_t*>(&h);
}
__device__ __forceinline__ uint32_t packbf(float a, float b) {
    __nv_bfloat162 h = __floats2bfloat162_rn(a, b);
    return *reinterpret_cast<uint32_t*>(&h);
}

__global__ void zero2_kernel(float4* a, int na4, float4* b, int nb4) {
    int i = blockIdx.x * blockDim.x + threadIdx.x;
    if (i < na4) a[i] = make_float4(0.f, 0.f, 0.f, 0.f);
    else if (i - na4 < nb4) b[i - na4] = make_float4(0.f, 0.f, 0.f, 0.f);
}

// ---------------- degrees ----------------------------------------------------
__global__ void degree_kernel(const int* __restrict__ src, const int* __restrict__ dst) {
    int i = blockIdx.x * blockDim.x + threadIdx.x;
    if (i < RE) {
        int r = i / Ee;
        atomicAdd(&g_cout[r * Nn + src[i]], 1);
        atomicAdd(&g_cin [r * Nn + dst[i]], 1);
    }
}
__global__ void rsq_kernel() {
    int i = blockIdx.x * blockDim.x + threadIdx.x;
    if (i < RN) {
        g_rso[i] = rsqrtf((float)max(g_cout[i], 1));
        g_rsi[i] = rsqrtf((float)max(g_cin [i], 1));
    }
}

// ---------------- CSR build: scan + fill --------------------------------------
__global__ void scan1_kernel() {   // per-1024-block exclusive scan of g_cin -> g_rp
    __shared__ int ts[256];
    int b = blockIdx.x, t = threadIdx.x;
    int i0 = b * 1024 + t * 4;
    int v0 = (i0 + 0 < RN) ? g_cin[i0 + 0] : 0;
    int v1 = (i0 + 1 < RN) ? g_cin[i0 + 1] : 0;
    int v2 = (i0 + 2 < RN) ? g_cin[i0 + 2] : 0;
    int v3 = (i0 + 3 < RN) ? g_cin[i0 + 3] : 0;
    int tot = v0 + v1 + v2 + v3;
    ts[t] = tot;
    __syncthreads();
    for (int off = 1; off < 256; off <<= 1) {
        int x = (t >= off) ? ts[t - off] : 0;
        __syncthreads();
        ts[t] += x;
        __syncthreads();
    }
    int excl = ts[t] - tot;
    if (i0 + 0 < RN) g_rp[i0 + 0] = excl;
    if (i0 + 1 < RN) g_rp[i0 + 1] = excl + v0;
    if (i0 + 2 < RN) g_rp[i0 + 2] = excl + v0 + v1;
    if (i0 + 3 < RN) g_rp[i0 + 3] = excl + v0 + v1 + v2;
    if (t == 255) g_bs[b] = ts[255];
}
__global__ void scan2_kernel(int nb) {   // single block, exclusive scan of block sums
    __shared__ int ts[512];
    int t = threadIdx.x;
    int v = (t < nb) ? g_bs[t] : 0;
    ts[t] = v;
    __syncthreads();
    for (int off = 1; off < 512; off <<= 1) {
        int x = (t >= off) ? ts[t - off] : 0;
        __syncthreads();
        ts[t] += x;
        __syncthreads();
    }
    g_bs[t] = ts[t] - v;
}
__global__ void scan3_kernel() {
    int b = blockIdx.x, t = threadIdx.x;
    int add = g_bs[b];
    int i0 = b * 1024 + t * 4;
#pragma unroll
    for (int q = 0; q < 4; ++q)
        if (i0 + q < RN) g_rp[i0 + q] += add;
    if (b == 0 && t == 0) g_rp[RN] = RE;
}
__global__ void fill_kernel(const int* __restrict__ src, const int* __restrict__ dst) {
    int i = blockIdx.x * blockDim.x + threadIdx.x;
    if (i >= RE) return;
    int r = i / Ee;
    int s = src[i];
    int idx = r * Nn + dst[i];
    int pos = g_rp[idx] + atomicAdd(&g_cin[idx], 1);   // g_cin re-zeroed before
    g_eidx[pos] = s;
    g_escale[pos] = g_rso[r * Nn + s];
}

// ---------------- weight prep: stacked bf16 hi/lo planes ---------------------
// Wst[l] planes: hi[n][r*64+ku], lo at +Hh*KU_L; source W_r[k][n].
__global__ void wprep_kernel(const float* __restrict__ W1,
                             const float* __restrict__ W2,
                             const float* __restrict__ Win) {
    int i = blockIdx.x * blockDim.x + threadIdx.x;
    const int TL = 2 * Hh * KU_L;   // 65536
    if (i < TL) {
        int l = i >> 15;
        int rem = i & 32767;
        int n = rem >> 8, j = rem & 255;
        int r = j >> 6, ku = j & 63;
        const float* W = (l == 0 ? W1 : W2) + (size_t)r * Hh * Hh;
        float w0 = W[(2 * ku) * Hh + n];
        float w1 = W[(2 * ku + 1) * Hh + n];
        float r0, r1;
        uint32_t hi = packbf_hi(w0, w1, r0, r1);
        size_t base = (size_t)l * WST;
        g_wst[base + (size_t)n * KU_L + j] = hi;
        g_wst[base + (size_t)Hh * KU_L + (size_t)n * KU_L + j] = packbf(r0, r1);
    } else {
        int j = i - TL;
        if (j < Hh * KU_I) {
            int n = j >> 5, ku = j & 31;
            float w0 = Win[(2 * ku) * Hh + n];
            float w1 = Win[(2 * ku + 1) * Hh + n];
            float r0, r1;
            uint32_t hi = packbf_hi(w0, w1, r0, r1);
            g_wtin[n * KU_I + ku] = hi;
            g_wtin[Hh * KU_I + n * KU_I + ku] = packbf(r0, r1);
        }
    }
}

__global__ void bsum_kernel(const float* __restrict__ b1,
                            const float* __restrict__ b2) {
    int j = threadIdx.x;
    if (j < Hh) {
        float s1 = 0.f, s2 = 0.f;
        for (int r = 0; r < Rr; ++r) { s1 += b1[r * Hh + j]; s2 += b2[r * Hh + j]; }
        g_bsum[j] = s1; g_bsum[Hh + j] = s2;
    }
}

// ---------------- fp32 -> bf16 hi/lo planes for x -----------------------------
__global__ void conv_kernel(const float* __restrict__ src, int KU2,
                            uint32_t* __restrict__ ph, uint32_t* __restrict__ pl,
                            int total) {
    int i = blockIdx.x * blockDim.x + threadIdx.x;
    if (i >= total) return;
    int row = i / KU2, ku = i - row * KU2;
    float2 f = *(const float2*)(src + (size_t)row * (2 * KU2) + 2 * ku);
    float r0, r1;
    ph[i] = packbf_hi(f.x, f.y, r0, r1);
    pl[i] = packbf(r0, r1);
}

// ---------------- CSR gather: agg planes, all relations ----------------------
// warp per node d: for each r, acc = rsi[r,d] * sum_e h[src]*escale; pack planes.
__global__ void gather_kernel(const float* __restrict__ h,
                              uint32_t* __restrict__ Ah, uint32_t* __restrict__ Al) {
    int w = (blockIdx.x * blockDim.x + threadIdx.x) >> 5;
    int lane = threadIdx.x & 31;
    if (w >= Nn) return;
#pragma unroll
    for (int r = 0; r < Rr; ++r) {
        int idx = r * Nn + w;
        int p0 = __ldg(&g_rp[idx]);
        int p1 = __ldg(&g_rp[idx + 1]);
        float4 acc = make_float4(0.f, 0.f, 0.f, 0.f);
        for (int p = p0; p < p1; ++p) {
            int s = __ldg(&g_eidx[p]);
            float sc = __ldg(&g_escale[p]);
            float4 v = *(const float4*)&h[(size_t)s * Hh + lane * 4];
            acc.x = fmaf(v.x, sc, acc.x);
            acc.y = fmaf(v.y, sc, acc.y);
            acc.z = fmaf(v.z, sc, acc.z);
            acc.w = fmaf(v.w, sc, acc.w);
        }
        float ri = __ldg(&g_rsi[idx]);
        acc.x *= ri; acc.y *= ri; acc.z *= ri; acc.w *= ri;
        float r0, r1, r2, r3;
        uint32_t h0 = packbf_hi(acc.x, acc.y, r0, r1);
        uint32_t h1 = packbf_hi(acc.z, acc.w, r2, r3);
        size_t base = (size_t)w * KU_L + r * 64 + 2 * lane;
        *(uint2*)&Ah[base] = make_uint2(h0, h1);
        *(uint2*)&Al[base] = make_uint2(packbf(r0, r1), packbf(r2, r3));
    }
}

// ---------------- bf16 3-pass GEMM (m16n8k16), plane A, cp.async pipeline ----
#define SMS 36
#define TILE_U (128 * SMS)

__device__ __forceinline__ void mma16(float* c, const uint32_t* a,
                                      uint32_t b0, uint32_t b1) {
    asm volatile(
        "mma.sync.aligned.m16n8k16.row.col.f32.bf16.bf16.f32 "
        "{%0,%1,%2,%3}, {%4,%5,%6,%7}, {%8,%9}, {%0,%1,%2,%3};"
        : "+f"(c[0]), "+f"(c[1]), "+f"(c[2]), "+f"(c[3])
        : "r"(a[0]), "r"(a[1]), "r"(a[2]), "r"(a[3]), "r"(b0), "r"(b1));
}
__device__ __forceinline__ void cpa16(uint32_t daddr, const uint32_t* src, uint32_t nbytes) {
    asm volatile("cp.async.cg.shared.global [%0], [%1], 16, %2;"
                 :: "r"(daddr), "l"(src), "r"(nbytes) : "memory");
}

__global__ void __launch_bounds__(256)
bf16_gemm_kernel(const uint32_t* __restrict__ Ah, const uint32_t* __restrict__ Al,
                 int KU,
                 const uint32_t* __restrict__ Wp,
                 const float* __restrict__ cbias,   // nullable
                 int relu_out,
                 float* __restrict__ C, int n) {
    extern __shared__ uint32_t smu[];

    const int tid = threadIdx.x;
    const int lane = tid & 31, warp = tid >> 5;
    const int wm = warp >> 1, wn = warp & 1;
    const int g = lane >> 2, t = lane & 3;
    const int row0 = blockIdx.x * 128;
    const int iters = KU >> 5;

    const int sr = tid >> 1;
    const int sc = (tid & 1) * 16;
    const int grow_s = row0 + sr;
    const int arow = (grow_s < n) ? grow_s : (n - 1);
    const uint32_t avalid = (grow_s < n) ? 16u : 0u;

    uint32_t smbase = (uint32_t)__cvta_generic_to_shared(smu);

    float acc[2][8][4];
#pragma unroll
    for (int mf = 0; mf < 2; ++mf)
#pragma unroll
        for (int nf = 0; nf < 8; ++nf)
#pragma unroll
            for (int q = 0; q < 4; ++q) acc[mf][nf][q] = 0.f;

#define ISSUE(CI) do {                                                         \
    const int uc_ = (CI) * 32 + sc;                                            \
    const uint32_t dbase_ = smbase + ((CI) & 1) * (4 * TILE_U * 4);            \
    const uint32_t doff_ = (sr * SMS + sc) * 4;                                \
    const uint32_t* pAh_ = Ah + (size_t)arow * KU + uc_;                       \
    const uint32_t* pAl_ = Al + (size_t)arow * KU + uc_;                       \
    const uint32_t* pWh_ = Wp + (size_t)sr * KU + uc_;                         \
    const uint32_t* pWl_ = pWh_ + (size_t)Hh * KU;                             \
    _Pragma("unroll")                                                          \
    for (int q = 0; q < 4; ++q) {                                              \
        cpa16(dbase_ + doff_ + q * 16,                  pAh_ + q * 4, avalid); \
        cpa16(dbase_ + TILE_U * 4 + doff_ + q * 16,     pAl_ + q * 4, avalid); \
        cpa16(dbase_ + 2 * TILE_U * 4 + doff_ + q * 16, pWh_ + q * 4, 16u);    \
        cpa16(dbase_ + 3 * TILE_U * 4 + doff_ + q * 16, pWl_ + q * 4, 16u);    \
    }                                                                          \
    asm volatile("cp.async.commit_group;" ::: "memory");                       \
} while (0)

    ISSUE(0);
    if (iters > 1) ISSUE(1);

    for (int ci = 0; ci < iters; ++ci) {
        if (ci + 1 < iters)
            asm volatile("cp.async.wait_group 1;" ::: "memory");
        else
            asm volatile("cp.async.wait_group 0;" ::: "memory");
        __syncthreads();

        const uint32_t* base = smu + (ci & 1) * (4 * TILE_U);
#pragma unroll
        for (int ks = 0; ks < 12; ++ks) {
            const int p = ks >> 2;
            const int kk = (ks & 3) * 8;
            const uint32_t* at = base + ((p == 1) ? TILE_U : 0);
            const uint32_t* bt = base + 2 * TILE_U + ((p == 2) ? TILE_U : 0);
            uint32_t a[2][4];
#pragma unroll
            for (int mf = 0; mf < 2; ++mf) {
                int r_ = wm * 32 + mf * 16 + g;
                a[mf][0] = at[(r_    ) * SMS + kk + t    ];
                a[mf][1] = at[(r_ + 8) * SMS + kk + t    ];
                a[mf][2] = at[(r_    ) * SMS + kk + t + 4];
                a[mf][3] = at[(r_ + 8) * SMS + kk + t + 4];
            }
#pragma unroll
            for (int nf = 0; nf < 8; ++nf) {
                int nr = wn * 64 + nf * 8 + g;
                uint32_t b0 = bt[nr * SMS + kk + t];
                uint32_t b1 = bt[nr * SMS + kk + t + 4];
                mma16(acc[0][nf], a[0], b0, b1);
                mma16(acc[1][nf], a[1], b0, b1);
            }
        }
        if (ci + 2 < iters) {
            __syncthreads();
            ISSUE(ci + 2);
        }
    }
#undef ISSUE

    // ---- epilogue (fp32, optional bias+relu)
#pragma unroll
    for (int mf = 0; mf < 2; ++mf) {
#pragma unroll
        for (int half = 0; half < 2; ++half) {
            int grow = row0 + wm * 32 + mf * 16 + g + half * 8;
            if (grow >= n) continue;
            float* crow = C + (size_t)grow * 128;
#pragma unroll
            for (int nf = 0; nf < 8; ++nf) {
                int col = wn * 64 + nf * 8 + 2 * t;
                float v0 = acc[mf][nf][half * 2 + 0];
                float v1 = acc[mf][nf][half * 2 + 1];
                if (cbias) { v0 += cbias[col]; v1 += cbias[col + 1]; }
                if (relu_out) { v0 = fmaxf(v0, 0.f); v1 = fmaxf(v1, 0.f); }
                float2 v; v.x = v0; v.y = v1;
                *(float2*)(crow + col) = v;
            }
        }
    }
}

// ---------------- pooling ----------------------------------------------------
__device__ __forceinline__ void red_add_v4(float* p, float4 v) {
    asm volatile(
        "{\n\t.reg .u64 pg;\n\t"
        "cvta.to.global.u64 pg, %0;\n\t"
        "red.global.add.v4.f32 [pg], {%1,%2,%3,%4};\n\t}"
        :: "l"(p), "f"(v.x), "f"(v.y), "f"(v.z), "f"(v.w) : "memory");
}
__global__ void count_kernel(const int* __restrict__ gid) {
    int i = blockIdx.x * blockDim.x + threadIdx.x;
    if (i < Nn) atomicAdd(&g_cnt[gid[i]], 1.f);
}
__global__ void pool_kernel(const float* __restrict__ h, const int* __restrict__ gid) {
    int t = blockIdx.x * blockDim.x + threadIdx.x;
    int node = t >> 5;
    int lane = t & 31;
    if (node >= Nn) return;
    int g = __ldg(&gid[node]);
    float4 v = *(const float4*)&h[(size_t)node * Hh + lane * 4];
    red_add_v4(&g_pool[g * Hh + lane * 4], v);
}

// ---------------- MLP head (single block) -------------------------------------
__global__ void mlp_kernel(const float* __restrict__ Wm1, const float* __restrict__ bm1,
                           const float* __restrict__ Wm2, const float* __restrict__ bm2,
                           const float* __restrict__ Wm3, const float* __restrict__ bm3,
                           float* __restrict__ out) {
    __shared__ float z[Gg * Hh];
    int tid = threadIdx.x;   // 256
    for (int i = tid; i < Gg * Hh; i += 256)
        z[i] = g_pool[i] / fmaxf(g_cnt[i >> 7], 1.f) + g_bsum[Hh + (i & 127)];
    __syncthreads();
    float r1[32];
#pragma unroll
    for (int t = 0; t < 32; ++t) {
        int o = tid + t * 256, g = o >> 7, j = o & 127;
        float s = bm1[j];
        for (int k = 0; k < Hh; ++k) s += z[(g << 7) + k] * Wm1[k * Hh + j];
        r1[t] = fmaxf(s, 0.f);
    }
    __syncthreads();
#pragma unroll
    for (int t = 0; t < 32; ++t) z[tid + t * 256] = r1[t];
    __syncthreads();
#pragma unroll
    for (int t = 0; t < 32; ++t) {
        int o = tid + t * 256, g = o >> 7, j = o & 127;
        float s = bm2[j];
        for (int k = 0; k < Hh; ++k) s += z[(g << 7) + k] * Wm2[k * Hh + j];
        r1[t] = fmaxf(s, 0.f);
    }
    __syncthreads();
#pragma unroll
    for (int t = 0; t < 32; ++t) z[tid + t * 256] = r1[t];
    __syncthreads();
    if (tid < Gg * Cc) {
        int g = tid >> 1, c = tid & 1;
        float s = bm3[c];
        for (int k = 0; k < Hh; ++k) s += z[(g << 7) + k] * Wm3[k * Cc + c];
        out[tid] = s;
    }
}

// ---------------- launch -------------------------------------------------------
static void* symv(const void* s) {
    void* p = nullptr;
    cudaGetSymbolAddress(&p, s);
    return p;
}

extern "C" void kernel_launch(void* const* d_in, const int* in_sizes, int n_in,
                              void* d_out, int out_size) {
    const float* x    = (const float*)d_in[0];
    const int*   src  = (const int*)  d_in[1];
    const int*   dst  = (const int*)  d_in[2];
    const int*   gid  = (const int*)  d_in[3];
    const float* W_in = (const float*)d_in[4];
    const float* b_in = (const float*)d_in[5];
    const float* W1   = (const float*)d_in[6];
    const float* b1   = (const float*)d_in[7];
    const float* W2   = (const float*)d_in[8];
    const float* b2   = (const float*)d_in[9];
    const float* Wm1  = (const float*)d_in[10];
    const float* bm1  = (const float*)d_in[11];
    const float* Wm2  = (const float*)d_in[12];
    const float* bm2  = (const float*)d_in[13];
    const float* Wm3  = (const float*)d_in[14];
    const float* bm3  = (const float*)d_in[15];
    float* out = (float*)d_out;

    float*    p_h    = (float*)   symv(g_h);
    float*    p_out2 = (float*)   symv(g_out2);
    int*      p_cout = (int*)     symv(g_cout);
    int*      p_cin  = (int*)     symv(g_cin);
    float*    p_pool = (float*)   symv(g_pool);
    float*    p_cnt  = (float*)   symv(g_cnt);
    uint32_t* p_wst  = (uint32_t*)symv(g_wst);
    uint32_t* p_wtin = (uint32_t*)symv(g_wtin);
    float*    p_bsum = (float*)   symv(g_bsum);
    uint32_t* p_Ah   = (uint32_t*)symv(g_Ah);
    uint32_t* p_Al   = (uint32_t*)symv(g_Al);

    const int TB = 256;
    const int gemm_blocks = (Nn + 127) / 128;       // 782
    const int scan_blocks = (RN + 1023) / 1024;     // 391
    const int smem_gemm = 8 * TILE_U * 4;           // 147456 bytes

    cudaFuncSetAttribute(bf16_gemm_kernel,
                         cudaFuncAttributeMaxDynamicSharedMemorySize, smem_gemm);

    // --- CSR + degrees
    zero2_kernel<<<(RN / 2 + TB - 1) / TB, TB>>>((float4*)p_cout, RN / 4,
                                                 (float4*)p_cin, RN / 4);
    degree_kernel<<<(RE + TB - 1) / TB, TB>>>(src, dst);
    rsq_kernel<<<(RN + TB - 1) / TB, TB>>>();
    scan1_kernel<<<scan_blocks, 256>>>();
    scan2_kernel<<<1, 512>>>(scan_blocks);
    scan3_kernel<<<scan_blocks, 256>>>();
    zero2_kernel<<<(RN / 4 + TB - 1) / TB, TB>>>((float4*)p_cin, RN / 4,
                                                 (float4*)p_cin, 0);
    fill_kernel<<<(RE + TB - 1) / TB, TB>>>(src, dst);

    // --- weights / biases
    wprep_kernel<<<(2 * Hh * KU_L + Hh * KU_I + TB - 1) / TB, TB>>>(W1, W2, W_in);
    bsum_kernel<<<1, 128>>>(b1, b2);

    // --- input: x -> planes -> h0 = relu(x@Win + b_in)
    conv_kernel<<<(Nn * KU_I + TB - 1) / TB, TB>>>(x, KU_I, p_Ah, p_Al, Nn * KU_I);
    bf16_gemm_kernel<<<gemm_blocks, 256, smem_gemm>>>(
        p_Ah, p_Al, KU_I, p_wtin, b_in, 1, p_h, Nn);

    // --- layer 1: gather -> stacked GEMM -> h1 = relu(. + bsum1)
    gather_kernel<<<(Nn * 32 + TB - 1) / TB, TB>>>(p_h, p_Ah, p_Al);
    bf16_gemm_kernel<<<gemm_blocks, 256, smem_gemm>>>(
        p_Ah, p_Al, KU_L, p_wst, p_bsum, 1, p_h, Nn);

    // --- layer 2: gather -> stacked GEMM -> out2 (raw; bsum2 folded into mlp)
    gather_kernel<<<(Nn * 32 + TB - 1) / TB, TB>>>(p_h, p_Ah, p_Al);
    bf16_gemm_kernel<<<gemm_blocks, 256, smem_gemm>>>(
        p_Ah, p_Al, KU_L, p_wst + (size_t)WST, nullptr, 0, p_out2, Nn);

    // --- pool + head
    zero2_kernel<<<(Gg * Hh / 4 + Gg / 4 + TB - 1) / TB, TB>>>(
        (float4*)p_pool, Gg * Hh / 4, (float4*)p_cnt, Gg / 4);
    count_kernel<<<(Nn + TB - 1) / TB, TB>>>(gid);
    pool_kernel<<<(Nn * 32 + TB - 1) / TB, TB>>>(p_out2, gid);
    mlp_kernel<<<1, TB>>>(Wm1, bm1, Wm2, bm2, Wm3, bm3, out);
}

// round 10
// speedup vs baseline: 2.6403x; 1.1340x over previous
#include <cuda_runtime.h>
#include <cuda_bf16.h>
#include <math.h>
#include <stdint.h>

// Problem constants (fixed by the reference)
#define Nn 100000
#define Ee 400000
#define Rr 4
#define Gg 64
#define INF 64
#define Hh 128
#define Cc 2
#define RN (Rr * Nn)        // 400000
#define RE (Rr * Ee)        // 1600000

#define KU_L 256            // stacked K for layer GEMMs (512 k / 2)
#define KU_I 32             // input GEMM (64 k / 2)
#define WST  (2 * Hh * KU_L)
#define WST_IN (2 * Hh * KU_I)

// ---------------- scratch (device globals; no allocation allowed) ----------
__device__ float    g_h   [(size_t)Nn * Hh];
__device__ float    g_out2[(size_t)Nn * Hh];
__device__ float    g_rso [RN];
__device__ float    g_rsi [RN];
__device__ int      g_cout[RN];
__device__ int      g_cin [RN];
__device__ int      g_rp  [RN + 1];
__device__ int      g_bs  [512];
__device__ int      g_eidx  [RE];
__device__ float    g_escale[RE];
__device__ uint32_t g_wst   [2 * WST];
__device__ uint32_t g_wtin  [WST_IN];
__device__ float    g_bsum  [2 * Hh];
__device__ uint32_t g_Ah[(size_t)Nn * KU_L];
__device__ uint32_t g_Al[(size_t)Nn * KU_L];
__device__ float    g_pool[Gg * Hh];
__device__ float    g_cnt [Gg];

// ---------------- helpers ----------------------------------------------------
__device__ __forceinline__ uint32_t packbf_hi(float a, float b, float& ra, float& rb) {
    __nv_bfloat162 h = __floats2bfloat162_rn(a, b);
    ra = a - __bfloat162float(h.x);
    rb = b - __bfloat162float(h.y);
    return *reinterpret_cast<uint32_t*>(&h);
}
__device__ __forceinline__ uint32_t packbf(float a, float b) {
    __nv_bfloat162 h = __floats2bfloat162_rn(a, b);
    return *reinterpret_cast<uint32_t*>(&h);
}

__global__ void zero2_kernel(float4* a, int na4, float4* b, int nb4) {
    int i = blockIdx.x * blockDim.x + threadIdx.x;
    if (i < na4) a[i] = make_float4(0.f, 0.f, 0.f, 0.f);
    else if (i - na4 < nb4) b[i - na4] = make_float4(0.f, 0.f, 0.f, 0.f);
}

// ---------------- degrees ----------------------------------------------------
__global__ void degree_kernel(const int* __restrict__ src, const int* __restrict__ dst) {
    int i = blockIdx.x * blockDim.x + threadIdx.x;
    if (i < RE) {
        int r = i / Ee;
        atomicAdd(&g_cout[r * Nn + src[i]], 1);
        atomicAdd(&g_cin [r * Nn + dst[i]], 1);
    }
}
__global__ void rsq_kernel() {
    int i = blockIdx.x * blockDim.x + threadIdx.x;
    if (i < RN) {
        g_rso[i] = rsqrtf((float)max(g_cout[i], 1));
        g_rsi[i] = rsqrtf((float)max(g_cin [i], 1));
    }
}

// ---------------- CSR build: scan + fill --------------------------------------
__global__ void scan1_kernel() {
    __shared__ int ts[256];
    int b = blockIdx.x, t = threadIdx.x;
    int i0 = b * 1024 + t * 4;
    int v0 = (i0 + 0 < RN) ? g_cin[i0 + 0] : 0;
    int v1 = (i0 + 1 < RN) ? g_cin[i0 + 1] : 0;
    int v2 = (i0 + 2 < RN) ? g_cin[i0 + 2] : 0;
    int v3 = (i0 + 3 < RN) ? g_cin[i0 + 3] : 0;
    int tot = v0 + v1 + v2 + v3;
    ts[t] = tot;
    __syncthreads();
    for (int off = 1; off < 256; off <<= 1) {
        int x = (t >= off) ? ts[t - off] : 0;
        __syncthreads();
        ts[t] += x;
        __syncthreads();
    }
    int excl = ts[t] - tot;
    if (i0 + 0 < RN) g_rp[i0 + 0] = excl;
    if (i0 + 1 < RN) g_rp[i0 + 1] = excl + v0;
    if (i0 + 2 < RN) g_rp[i0 + 2] = excl + v0 + v1;
    if (i0 + 3 < RN) g_rp[i0 + 3] = excl + v0 + v1 + v2;
    if (t == 255) g_bs[b] = ts[255];
}
__global__ void scan2_kernel(int nb) {
    __shared__ int ts[512];
    int t = threadIdx.x;
    int v = (t < nb) ? g_bs[t] : 0;
    ts[t] = v;
    __syncthreads();
    for (int off = 1; off < 512; off <<= 1) {
        int x = (t >= off) ? ts[t - off] : 0;
        __syncthreads();
        ts[t] += x;
        __syncthreads();
    }
    g_bs[t] = ts[t] - v;
}
__global__ void scan3_kernel() {
    int b = blockIdx.x, t = threadIdx.x;
    int add = g_bs[b];
    int i0 = b * 1024 + t * 4;
#pragma unroll
    for (int q = 0; q < 4; ++q)
        if (i0 + q < RN) g_rp[i0 + q] += add;
    if (b == 0 && t == 0) g_rp[RN] = RE;
}
__global__ void fill_kernel(const int* __restrict__ src, const int* __restrict__ dst) {
    int i = blockIdx.x * blockDim.x + threadIdx.x;
    if (i >= RE) return;
    int r = i / Ee;
    int s = src[i];
    int idx = r * Nn + dst[i];
    int pos = g_rp[idx] + atomicAdd(&g_cin[idx], 1);
    g_eidx[pos] = s;
    g_escale[pos] = g_rso[r * Nn + s];
}

// ---------------- weight prep ---------------------------------------------------
__global__ void wprep_kernel(const float* __restrict__ W1,
                             const float* __restrict__ W2,
                             const float* __restrict__ Win) {
    int i = blockIdx.x * blockDim.x + threadIdx.x;
    const int TL = 2 * Hh * KU_L;
    if (i < TL) {
        int l = i >> 15;
        int rem = i & 32767;
        int n = rem >> 8, j = rem & 255;
        int r = j >> 6, ku = j & 63;
        const float* W = (l == 0 ? W1 : W2) + (size_t)r * Hh * Hh;
        float w0 = W[(2 * ku) * Hh + n];
        float w1 = W[(2 * ku + 1) * Hh + n];
        float r0, r1;
        uint32_t hi = packbf_hi(w0, w1, r0, r1);
        size_t base = (size_t)l * WST;
        g_wst[base + (size_t)n * KU_L + j] = hi;
        g_wst[base + (size_t)Hh * KU_L + (size_t)n * KU_L + j] = packbf(r0, r1);
    } else {
        int j = i - TL;
        if (j < Hh * KU_I) {
            int n = j >> 5, ku = j & 31;
            float w0 = Win[(2 * ku) * Hh + n];
            float w1 = Win[(2 * ku + 1) * Hh + n];
            float r0, r1;
            uint32_t hi = packbf_hi(w0, w1, r0, r1);
            g_wtin[n * KU_I + ku] = hi;
            g_wtin[Hh * KU_I + n * KU_I + ku] = packbf(r0, r1);
        }
    }
}

__global__ void bsum_kernel(const float* __restrict__ b1,
                            const float* __restrict__ b2) {
    int j = threadIdx.x;
    if (j < Hh) {
        float s1 = 0.f, s2 = 0.f;
        for (int r = 0; r < Rr; ++r) { s1 += b1[r * Hh + j]; s2 += b2[r * Hh + j]; }
        g_bsum[j] = s1; g_bsum[Hh + j] = s2;
    }
}

// ---------------- fp32 -> bf16 hi/lo planes for x -----------------------------
__global__ void conv_kernel(const float* __restrict__ src, int KU2,
                            uint32_t* __restrict__ ph, uint32_t* __restrict__ pl,
                            int total) {
    int i = blockIdx.x * blockDim.x + threadIdx.x;
    if (i >= total) return;
    int row = i / KU2, ku = i - row * KU2;
    float2 f = *(const float2*)(src + (size_t)row * (2 * KU2) + 2 * ku);
    float r0, r1;
    ph[i] = packbf_hi(f.x, f.y, r0, r1);
    pl[i] = packbf(r0, r1);
}

// ---------------- CSR gather ---------------------------------------------------
__global__ void gather_kernel(const float* __restrict__ h,
                              uint32_t* __restrict__ Ah, uint32_t* __restrict__ Al) {
    int w = (blockIdx.x * blockDim.x + threadIdx.x) >> 5;
    int lane = threadIdx.x & 31;
    if (w >= Nn) return;
#pragma unroll
    for (int r = 0; r < Rr; ++r) {
        int idx = r * Nn + w;
        int p0 = __ldg(&g_rp[idx]);
        int p1 = __ldg(&g_rp[idx + 1]);
        float4 acc = make_float4(0.f, 0.f, 0.f, 0.f);
        for (int p = p0; p < p1; ++p) {
            int s = __ldg(&g_eidx[p]);
            float sc = __ldg(&g_escale[p]);
            float4 v = *(const float4*)&h[(size_t)s * Hh + lane * 4];
            acc.x = fmaf(v.x, sc, acc.x);
            acc.y = fmaf(v.y, sc, acc.y);
            acc.z = fmaf(v.z, sc, acc.z);
            acc.w = fmaf(v.w, sc, acc.w);
        }
        float ri = __ldg(&g_rsi[idx]);
        acc.x *= ri; acc.y *= ri; acc.z *= ri; acc.w *= ri;
        float r0, r1, r2, r3;
        uint32_t h0 = packbf_hi(acc.x, acc.y, r0, r1);
        uint32_t h1 = packbf_hi(acc.z, acc.w, r2, r3);
        size_t base = (size_t)w * KU_L + r * 64 + 2 * lane;
        *(uint2*)&Ah[base] = make_uint2(h0, h1);
        *(uint2*)&Al[base] = make_uint2(packbf(r0, r1), packbf(r2, r3));
    }
}

// ---------------- bf16 3-pass GEMM: 512 threads, 3-stage cp.async ------------
#define SMS 36
#define TILE_U (128 * SMS)
#define STAGE_U (4 * TILE_U)          // 4 planes per stage (u32)

__device__ __forceinline__ void mma16(float* c, const uint32_t* a,
                                      uint32_t b0, uint32_t b1) {
    asm volatile(
        "mma.sync.aligned.m16n8k16.row.col.f32.bf16.bf16.f32 "
        "{%0,%1,%2,%3}, {%4,%5,%6,%7}, {%8,%9}, {%0,%1,%2,%3};"
        : "+f"(c[0]), "+f"(c[1]), "+f"(c[2]), "+f"(c[3])
        : "r"(a[0]), "r"(a[1]), "r"(a[2]), "r"(a[3]), "r"(b0), "r"(b1));
}
__device__ __forceinline__ void cpa16(uint32_t daddr, const uint32_t* src, uint32_t nbytes) {
    asm volatile("cp.async.cg.shared.global [%0], [%1], 16, %2;"
                 :: "r"(daddr), "l"(src), "r"(nbytes) : "memory");
}

__global__ void __launch_bounds__(512)
bf16_gemm_kernel(const uint32_t* __restrict__ Ah, const uint32_t* __restrict__ Al,
                 int KU,
                 const uint32_t* __restrict__ Wp,
                 const float* __restrict__ cbias,   // nullable
                 int relu_out,
                 float* __restrict__ C, int n) {
    extern __shared__ uint32_t smu[];

    const int tid = threadIdx.x;
    const int lane = tid & 31, warp = tid >> 5;   // 16 warps
    const int wm = warp >> 1, wn = warp & 1;      // wm 0..7 (16 rows), wn 0..1 (64 cols)
    const int g = lane >> 2, t = lane & 3;
    const int row0 = blockIdx.x * 128;
    const int iters = KU >> 5;

    // staging: 4 threads per row, each 8 u32 (32B) per plane
    const int sr = tid >> 2;            // 0..127
    const int sc = (tid & 3) * 8;       // 0,8,16,24
    const int grow_s = row0 + sr;
    const int arow = (grow_s < n) ? grow_s : (n - 1);
    const uint32_t avalid = (grow_s < n) ? 16u : 0u;

    uint32_t smbase = (uint32_t)__cvta_generic_to_shared(smu);

    float acc[8][4];
#pragma unroll
    for (int nf = 0; nf < 8; ++nf)
#pragma unroll
        for (int q = 0; q < 4; ++q) acc[nf][q] = 0.f;

#define ISSUE(CI) do {                                                         \
    const int uc_ = (CI) * 32 + sc;                                            \
    const uint32_t dbase_ = smbase + ((CI) % 3) * (STAGE_U * 4);               \
    const uint32_t doff_ = (sr * SMS + sc) * 4;                                \
    const uint32_t* pAh_ = Ah + (size_t)arow * KU + uc_;                       \
    const uint32_t* pAl_ = Al + (size_t)arow * KU + uc_;                       \
    const uint32_t* pWh_ = Wp + (size_t)sr * KU + uc_;                         \
    const uint32_t* pWl_ = pWh_ + (size_t)Hh * KU;                             \
    _Pragma("unroll")                                                          \
    for (int q = 0; q < 2; ++q) {                                              \
        cpa16(dbase_ + doff_ + q * 16,                  pAh_ + q * 4, avalid); \
        cpa16(dbase_ + TILE_U * 4 + doff_ + q * 16,     pAl_ + q * 4, avalid); \
        cpa16(dbase_ + 2 * TILE_U * 4 + doff_ + q * 16, pWh_ + q * 4, 16u);    \
        cpa16(dbase_ + 3 * TILE_U * 4 + doff_ + q * 16, pWl_ + q * 4, 16u);    \
    }                                                                          \
    asm volatile("cp.async.commit_group;" ::: "memory");                       \
} while (0)

    ISSUE(0);
    if (iters > 1) ISSUE(1);

    for (int ci = 0; ci < iters; ++ci) {
        if (ci + 1 < iters)
            asm volatile("cp.async.wait_group 1;" ::: "memory");
        else
            asm volatile("cp.async.wait_group 0;" ::: "memory");
        __syncthreads();
        if (ci + 2 < iters) ISSUE(ci + 2);   // overwrites stage (ci-1)%3: safe post-sync

        const uint32_t* base = smu + (ci % 3) * STAGE_U;
#pragma unroll
        for (int ks = 0; ks < 12; ++ks) {
            const int p = ks >> 2;
            const int kk = (ks & 3) * 8;
            const uint32_t* at = base + ((p == 1) ? TILE_U : 0);
            const uint32_t* bt = base + 2 * TILE_U + ((p == 2) ? TILE_U : 0);
            const int r_ = wm * 16 + g;
            uint32_t a[4];
            a[0] = at[(r_    ) * SMS + kk + t    ];
            a[1] = at[(r_ + 8) * SMS + kk + t    ];
            a[2] = at[(r_    ) * SMS + kk + t + 4];
            a[3] = at[(r_ + 8) * SMS + kk + t + 4];
#pragma unroll
            for (int nf = 0; nf < 8; ++nf) {
                int nr = wn * 64 + nf * 8 + g;
                uint32_t b0 = bt[nr * SMS + kk + t];
                uint32_t b1 = bt[nr * SMS + kk + t + 4];
                mma16(acc[nf], a, b0, b1);
            }
        }
    }
#undef ISSUE

    // ---- epilogue
#pragma unroll
    for (int half = 0; half < 2; ++half) {
        int grow = row0 + wm * 16 + g + half * 8;
        if (grow >= n) continue;
        float* crow = C + (size_t)grow * 128;
#pragma unroll
        for (int nf = 0; nf < 8; ++nf) {
            int col = wn * 64 + nf * 8 + 2 * t;
            float v0 = acc[nf][half * 2 + 0];
            float v1 = acc[nf][half * 2 + 1];
            if (cbias) { v0 += cbias[col]; v1 += cbias[col + 1]; }
            if (relu_out) { v0 = fmaxf(v0, 0.f); v1 = fmaxf(v1, 0.f); }
            float2 v; v.x = v0; v.y = v1;
            *(float2*)(crow + col) = v;
        }
    }
}

// ---------------- pooling (sorted-run accumulation) ---------------------------
__device__ __forceinline__ void red_add_v4(float* p, float4 v) {
    asm volatile(
        "{\n\t.reg .u64 pg;\n\t"
        "cvta.to.global.u64 pg, %0;\n\t"
        "red.global.add.v4.f32 [pg], {%1,%2,%3,%4};\n\t}"
        :: "l"(p), "f"(v.x), "f"(v.y), "f"(v.z), "f"(v.w) : "memory");
}
__global__ void count_kernel(const int* __restrict__ gid) {
    int i = blockIdx.x * blockDim.x + threadIdx.x;
    if (i < Nn) atomicAdd(&g_cnt[gid[i]], 1.f);
}
// warp handles 16 consecutive nodes; gid sorted -> few flushes
__global__ void pool_kernel(const float* __restrict__ h, const int* __restrict__ gid) {
    int w = (blockIdx.x * blockDim.x + threadIdx.x) >> 5;
    int lane = threadIdx.x & 31;
    int n0 = w * 16;
    if (n0 >= Nn) return;
    int n1 = min(n0 + 16, Nn);
    int curg = __ldg(&gid[n0]);
    float4 acc = make_float4(0.f, 0.f, 0.f, 0.f);
    for (int node = n0; node < n1; ++node) {
        int g = __ldg(&gid[node]);
        if (g != curg) {
            red_add_v4(&g_pool[curg * Hh + lane * 4], acc);
            acc = make_float4(0.f, 0.f, 0.f, 0.f);
            curg = g;
        }
        float4 v = *(const float4*)&h[(size_t)node * Hh + lane * 4];
        acc.x += v.x; acc.y += v.y; acc.z += v.z; acc.w += v.w;
    }
    red_add_v4(&g_pool[curg * Hh + lane * 4], acc);
}

// ---------------- MLP head (single block) -------------------------------------
__global__ void mlp_kernel(const float* __restrict__ Wm1, const float* __restrict__ bm1,
                           const float* __restrict__ Wm2, const float* __restrict__ bm2,
                           const float* __restrict__ Wm3, const float* __restrict__ bm3,
                           float* __restrict__ out) {
    __shared__ float z[Gg * Hh];
    int tid = threadIdx.x;   // 256
    for (int i = tid; i < Gg * Hh; i += 256)
        z[i] = g_pool[i] / fmaxf(g_cnt[i >> 7], 1.f) + g_bsum[Hh + (i & 127)];
    __syncthreads();
    float r1[32];
#pragma unroll
    for (int t = 0; t < 32; ++t) {
        int o = tid + t * 256, g = o >> 7, j = o & 127;
        float s = bm1[j];
        for (int k = 0; k < Hh; ++k) s += z[(g << 7) + k] * Wm1[k * Hh + j];
        r1[t] = fmaxf(s, 0.f);
    }
    __syncthreads();
#pragma unroll
    for (int t = 0; t < 32; ++t) z[tid + t * 256] = r1[t];
    __syncthreads();
#pragma unroll
    for (int t = 0; t < 32; ++t) {
        int o = tid + t * 256, g = o >> 7, j = o & 127;
        float s = bm2[j];
        for (int k = 0; k < Hh; ++k) s += z[(g << 7) + k] * Wm2[k * Hh + j];
        r1[t] = fmaxf(s, 0.f);
    }
    __syncthreads();
#pragma unroll
    for (int t = 0; t < 32; ++t) z[tid + t * 256] = r1[t];
    __syncthreads();
    if (tid < Gg * Cc) {
        int g = tid >> 1, c = tid & 1;
        float s = bm3[c];
        for (int k = 0; k < Hh; ++k) s += z[(g << 7) + k] * Wm3[k * Cc + c];
        out[tid] = s;
    }
}

// ---------------- launch -------------------------------------------------------
static void* symv(const void* s) {
    void* p = nullptr;
    cudaGetSymbolAddress(&p, s);
    return p;
}

extern "C" void kernel_launch(void* const* d_in, const int* in_sizes, int n_in,
                              void* d_out, int out_size) {
    const float* x    = (const float*)d_in[0];
    const int*   src  = (const int*)  d_in[1];
    const int*   dst  = (const int*)  d_in[2];
    const int*   gid  = (const int*)  d_in[3];
    const float* W_in = (const float*)d_in[4];
    const float* b_in = (const float*)d_in[5];
    const float* W1   = (const float*)d_in[6];
    const float* b1   = (const float*)d_in[7];
    const float* W2   = (const float*)d_in[8];
    const float* b2   = (const float*)d_in[9];
    const float* Wm1  = (const float*)d_in[10];
    const float* bm1  = (const float*)d_in[11];
    const float* Wm2  = (const float*)d_in[12];
    const float* bm2  = (const float*)d_in[13];
    const float* Wm3  = (const float*)d_in[14];
    const float* bm3  = (const float*)d_in[15];
    float* out = (float*)d_out;

    float*    p_h    = (float*)   symv(g_h);
    float*    p_out2 = (float*)   symv(g_out2);
    int*      p_cout = (int*)     symv(g_cout);
    int*      p_cin  = (int*)     symv(g_cin);
    float*    p_pool = (float*)   symv(g_pool);
    float*    p_cnt  = (float*)   symv(g_cnt);
    uint32_t* p_wst  = (uint32_t*)symv(g_wst);
    uint32_t* p_wtin = (uint32_t*)symv(g_wtin);
    float*    p_bsum = (float*)   symv(g_bsum);
    uint32_t* p_Ah   = (uint32_t*)symv(g_Ah);
    uint32_t* p_Al   = (uint32_t*)symv(g_Al);

    const int TB = 256;
    const int gemm_blocks = (Nn + 127) / 128;       // 782
    const int scan_blocks = (RN + 1023) / 1024;     // 391
    const int smem_gemm = 3 * STAGE_U * 4;          // 221184 bytes

    cudaFuncSetAttribute(bf16_gemm_kernel,
                         cudaFuncAttributeMaxDynamicSharedMemorySize, smem_gemm);

    // --- CSR + degrees
    zero2_kernel<<<(RN / 2 + TB - 1) / TB, TB>>>((float4*)p_cout, RN / 4,
                                                 (float4*)p_cin, RN / 4);
    degree_kernel<<<(RE + TB - 1) / TB, TB>>>(src, dst);
    rsq_kernel<<<(RN + TB - 1) / TB, TB>>>();
    scan1_kernel<<<scan_blocks, 256>>>();
    scan2_kernel<<<1, 512>>>(scan_blocks);
    scan3_kernel<<<scan_blocks, 256>>>();
    zero2_kernel<<<(RN / 4 + TB - 1) / TB, TB>>>((float4*)p_cin, RN / 4,
                                                 (float4*)p_cin, 0);
    fill_kernel<<<(RE + TB - 1) / TB, TB>>>(src, dst);

    // --- weights / biases
    wprep_kernel<<<(2 * Hh * KU_L + Hh * KU_I + TB - 1) / TB, TB>>>(W1, W2, W_in);
    bsum_kernel<<<1, 128>>>(b1, b2);

    // --- input: x -> planes -> h0 = relu(x@Win + b_in)
    conv_kernel<<<(Nn * KU_I + TB - 1) / TB, TB>>>(x, KU_I, p_Ah, p_Al, Nn * KU_I);
    bf16_gemm_kernel<<<gemm_blocks, 512, smem_gemm>>>(
        p_Ah, p_Al, KU_I, p_wtin, b_in, 1, p_h, Nn);

    // --- layer 1: gather -> stacked GEMM -> h1 = relu(. + bsum1)
    gather_kernel<<<(Nn * 32 + TB - 1) / TB, TB>>>(p_h, p_Ah, p_Al);
    bf16_gemm_kernel<<<gemm_blocks, 512, smem_gemm>>>(
        p_Ah, p_Al, KU_L, p_wst, p_bsum, 1, p_h, Nn);

    // --- layer 2: gather -> stacked GEMM -> out2 (raw; bsum2 folded into mlp)
    gather_kernel<<<(Nn * 32 + TB - 1) / TB, TB>>>(p_h, p_Ah, p_Al);
    bf16_gemm_kernel<<<gemm_blocks, 512, smem_gemm>>>(
        p_Ah, p_Al, KU_L, p_wst + (size_t)WST, nullptr, 0, p_out2, Nn);

    // --- pool + head
    zero2_kernel<<<(Gg * Hh / 4 + Gg / 4 + TB - 1) / TB, TB>>>(
        (float4*)p_pool, Gg * Hh / 4, (float4*)p_cnt, Gg / 4);
    count_kernel<<<(Nn + TB - 1) / TB, TB>>>(gid);
    pool_kernel<<<((Nn + 15) / 16 * 32 + TB - 1) / TB, TB>>>(p_out2, gid);
    mlp_kernel<<<1, TB>>>(Wm1, bm1, Wm2, bm2, Wm3, bm3, out);
}